// round 13
// baseline (speedup 1.0000x reference)
#include <cuda_runtime.h>
#include <cuda_fp16.h>
#include <math.h>
#include <cstdint>

#define TT 256
#define BB 128
#define HH 512
#define DEMB 256
#define PAD_IDX 29999
#define NCLS 5
#define G4H 2048  // 4*HH

#define BAR_SUB 8
#define BAR_SPC 32
#define BAR_STEP (BAR_SUB * BAR_SPC)
#define BAR_GRP  (TT * BAR_STEP)

__device__ __forceinline__ uint32_t smem_to_u32(const void* p) {
    uint32_t a;
    asm("{ .reg .u64 t; cvta.to.shared.u64 t, %1; cvt.u32.u64 %0, t; }" : "=r"(a) : "l"(p));
    return a;
}
#define CP_ASYNC16(dst, src) \
    asm volatile("cp.async.cg.shared.global [%0], [%1], 16;" :: "r"(dst), "l"(src))
#define CP_COMMIT  asm volatile("cp.async.commit_group;" ::: "memory")
#define CP_WAIT_1  asm volatile("cp.async.wait_group 1;" ::: "memory")
#define CP_WAIT_0  asm volatile("cp.async.wait_group 0;" ::: "memory")

// ========================= scratch (static, no allocs) =======================
__device__ __half g_x0 [(size_t)TT * BB * DEMB];
__device__ __half g_xg0f[(size_t)TT * BB * G4H];
__device__ __half g_xg0r[(size_t)TT * BB * G4H];
__device__ __half g_h0 [(size_t)TT * BB * 2 * HH];
__device__ __half g_xg1f[(size_t)TT * BB * G4H];
__device__ __half g_xg1r[(size_t)BB * G4H];
__device__ __half g_hf0[2 * 2 * BB * HH];
__device__ __half g_hf1[2 * BB * HH];
__device__ float g_h1f [BB * HH];
__device__ float g_hr1 [BB * HH];
__device__ int g_bar0[2 * BAR_GRP];
__device__ int g_bar1[2 * BAR_GRP];

__global__ void reset_kernel() {
    int n = 2 * BAR_GRP;
    for (int i = blockIdx.x * blockDim.x + threadIdx.x; i < n;
         i += gridDim.x * blockDim.x) {
        g_bar0[i] = 0;
        g_bar1[i] = 0;
    }
}

__device__ __forceinline__ uint32_t pack_h2(float a, float b) {
    __half2 h = __floats2half2_rn(a, b);
    return *(uint32_t*)&h;
}

__device__ __forceinline__ void bar_arrive_wait(int* base, int sub, int target) {
    atomicAdd(base + sub * BAR_SPC, 1);
    for (;;) {
        int sum = 0;
#pragma unroll
        for (int s = 0; s < BAR_SUB; s++) {
            int v;
            asm volatile("ld.global.cg.b32 %0, [%1];" : "=r"(v)
                         : "l"(base + s * BAR_SPC));
            sum += v;
        }
        if (sum >= target) break;
        __nanosleep(32);
    }
}

// ========================= embedding gather (fp16 out) =======================
__global__ void embed_kernel(const int* __restrict__ x,
                             const float* __restrict__ emb,
                             __half* __restrict__ out) {
    int gid = blockIdx.x * blockDim.x + threadIdx.x;
    if (gid >= TT * BB * (DEMB / 4)) return;
    int i4  = gid & 63;
    int row = gid >> 6;
    int t = row / BB;
    int b = row - t * BB;
    int xi = x[b * TT + t];
    float4 v;
    if (xi == PAD_IDX) { v.x = v.y = v.z = v.w = 0.f; }
    else               { v = ((const float4*)emb)[(size_t)xi * 64 + i4]; }
    uint2 p;
    p.x = pack_h2(v.x, v.y);
    p.y = pack_h2(v.z, v.w);
    ((uint2*)out)[gid] = p;
}

// ========================= mma primitives ====================================
__device__ __forceinline__ void ldsm4(uint32_t* r, uint32_t addr) {
    asm volatile("ldmatrix.sync.aligned.m8n8.x4.shared.b16 {%0,%1,%2,%3}, [%4];"
        : "=r"(r[0]), "=r"(r[1]), "=r"(r[2]), "=r"(r[3]) : "r"(addr));
}
__device__ __forceinline__ void mma_f16(float* d, const uint32_t* a,
                                        uint32_t b0, uint32_t b1) {
    asm volatile("mma.sync.aligned.m16n8k16.row.col.f32.f16.f16.f32 "
        "{%0,%1,%2,%3}, {%4,%5,%6,%7}, {%8,%9}, {%0,%1,%2,%3};"
        : "+f"(d[0]), "+f"(d[1]), "+f"(d[2]), "+f"(d[3])
        : "r"(a[0]), "r"(a[1]), "r"(a[2]), "r"(a[3]), "r"(b0), "r"(b1));
}
__device__ __forceinline__ void splitw_store(uint32_t hiA, uint32_t loA, float4 v) {
    __half h0 = __float2half_rn(v.x), h1 = __float2half_rn(v.y);
    __half h2 = __float2half_rn(v.z), h3 = __float2half_rn(v.w);
    float r0 = v.x - __half2float(h0), r1 = v.y - __half2float(h1);
    float r2 = v.z - __half2float(h2), r3 = v.w - __half2float(h3);
    uint32_t hp0 = pack_h2(__half2float(h0), __half2float(h1));
    uint32_t hp1 = pack_h2(__half2float(h2), __half2float(h3));
    uint32_t lp0 = pack_h2(r0, r1);
    uint32_t lp1 = pack_h2(r2, r3);
    asm volatile("st.shared.v2.b32 [%0], {%1, %2};" :: "r"(hiA), "r"(hp0), "r"(hp1) : "memory");
    asm volatile("st.shared.v2.b32 [%0], {%1, %2};" :: "r"(loA), "r"(lp0), "r"(lp1) : "memory");
}

// ========================= fp16-A GEMM: C(fp16) = A*W^T + bias ===============
#define KC  32
#define LDH 40
#define GA_BYTES (128 * LDH * 2)

__global__ __launch_bounds__(256, 2) void gemm_mma(const __half* __restrict__ A,
                                                   const float* __restrict__ W,
                                                   const float* __restrict__ bias,
                                                   __half* __restrict__ C,
                                                   int M, int N, int K) {
    __shared__ __align__(16) __half gsm[4 * 128 * LDH];
    const uint32_t sb  = smem_to_u32(gsm);
    const uint32_t AH0 = sb, AH1 = sb + GA_BYTES;
    const uint32_t BH  = sb + 2 * GA_BYTES, BL = BH + GA_BYTES;

    const int tid  = threadIdx.x;
    const int lane = tid & 31;
    const int wid  = tid >> 5;
    const int wm   = wid & 3;
    const int wn   = wid >> 2;
    const int bm   = blockIdx.y * 128;
    const int bn   = blockIdx.x * 128;

    float acc[2][8][4];
#pragma unroll
    for (int i = 0; i < 2; i++)
#pragma unroll
        for (int j = 0; j < 8; j++)
#pragma unroll
            for (int k = 0; k < 4; k++) acc[i][j][k] = 0.f;

    const uint32_t a_row = lane & 15;
    const uint32_t a_col = (lane >> 4) << 3;
    const uint32_t b_n   = (lane & 7) + ((lane >> 4) << 3);
    const uint32_t b_k   = ((lane >> 3) & 1) << 3;

    const int s_row = tid >> 2, s_c8 = tid & 3;
    const int w_row = tid >> 3, w_c4 = tid & 7;

    float4 vw[4];
#pragma unroll
    for (int i = 0; i < 2; i++) {
        int row = s_row + i * 64;
        CP_ASYNC16(AH0 + (row * LDH + s_c8 * 8) * 2,
                   A + (size_t)(bm + row) * K + s_c8 * 8);
    }
    CP_COMMIT;
#pragma unroll
    for (int i = 0; i < 4; i++) {
        int row = w_row + i * 32;
        vw[i] = *(const float4*)(W + (size_t)(bn + row) * K + w_c4 * 4);
    }

    const int nch = K / KC;
    for (int ch = 0; ch < nch; ch++) {
        const int kb = ch * KC;
        if (ch + 1 < nch) {
            uint32_t dst = ((ch + 1) & 1) ? AH1 : AH0;
#pragma unroll
            for (int i = 0; i < 2; i++) {
                int row = s_row + i * 64;
                CP_ASYNC16(dst + (row * LDH + s_c8 * 8) * 2,
                           A + (size_t)(bm + row) * K + kb + KC + s_c8 * 8);
            }
            CP_COMMIT;
        }
#pragma unroll
        for (int i = 0; i < 4; i++) {
            int row = w_row + i * 32;
            uint32_t off = (row * LDH + w_c4 * 4) * 2;
            splitw_store(BH + off, BL + off, vw[i]);
        }
        if (ch + 1 < nch) {
#pragma unroll
            for (int i = 0; i < 4; i++) {
                int row = w_row + i * 32;
                vw[i] = *(const float4*)(W + (size_t)(bn + row) * K + kb + KC + w_c4 * 4);
            }
        }
        if (ch + 1 < nch) { CP_WAIT_1; } else { CP_WAIT_0; }
        __syncthreads();

        const uint32_t AH = (ch & 1) ? AH1 : AH0;
#pragma unroll
        for (int ks = 0; ks < KC; ks += 16) {
            uint32_t ah[2][4];
#pragma unroll
            for (int ma = 0; ma < 2; ma++)
                ldsm4(ah[ma], AH + ((wm * 32 + ma * 16 + a_row) * LDH + ks + a_col) * 2);
#pragma unroll
            for (int bg = 0; bg < 4; bg++) {
                uint32_t boff = ((wn * 64 + bg * 16 + b_n) * LDH + ks + b_k) * 2;
                uint32_t bh[4], bl[4];
                ldsm4(bh, BH + boff);
                ldsm4(bl, BL + boff);
#pragma unroll
                for (int ma = 0; ma < 2; ma++) {
#pragma unroll
                    for (int na = 0; na < 2; na++) {
                        float* d = acc[ma][bg * 2 + na];
                        mma_f16(d, ah[ma], bh[na * 2], bh[na * 2 + 1]);
                        mma_f16(d, ah[ma], bl[na * 2], bl[na * 2 + 1]);
                    }
                }
            }
        }
        __syncthreads();
    }

#pragma unroll
    for (int ma = 0; ma < 2; ma++) {
        int row0 = bm + wm * 32 + ma * 16 + (lane >> 2);
#pragma unroll
        for (int na = 0; na < 8; na++) {
            int col = bn + wn * 64 + na * 8 + (lane & 3) * 2;
            float b0 = bias[col], b1 = bias[col + 1];
            *(uint32_t*)(C + (size_t)row0 * N + col) =
                pack_h2(acc[ma][na][0] + b0, acc[ma][na][1] + b1);
            *(uint32_t*)(C + (size_t)(row0 + 8) * N + col) =
                pack_h2(acc[ma][na][2] + b0, acc[ma][na][3] + b1);
        }
    }
}

__device__ __forceinline__ float sigmoidf_(float v) { return 1.f / (1.f + expf(-v)); }

// ========================= tensor-core LSTM scan =============================
#define W_STR 520
#define A_STR 264
#define W_SPL_BYTES (32 * W_STR * 2)
#define SCAN_W_BYTES (2 * W_SPL_BYTES)                    // 66560
#define SCAN0_SMEM (SCAN_W_BYTES + 2 * 128 * A_STR * 2)   // 201728
#define SCAN1_SMEM (SCAN_W_BYTES + 2 * 64 * A_STR * 2)    // 134144

template<int MC>
__device__ __forceinline__ void stage_chunk(uint32_t dst, const __half* hs,
                                            int bbase, int kb, int tid) {
#pragma unroll
    for (int i = 0; i < MC / 8; i++) {
        int e = tid + i * 256;
        int row = e >> 5, seg = e & 31;
        const __half* src = hs + (size_t)(bbase + row) * HH + kb + seg * 8;
        CP_ASYNC16(dst + (row * A_STR + seg * 8) * 2, src);
    }
}

// split hi/lo accumulators -> 8 independent HMMA chains per warp
__device__ __forceinline__ void mma_chunk2(uint32_t AB, uint32_t WHI, uint32_t WLO,
                                           int mrow, int kg0,
                                           uint32_t a_row, uint32_t a_col,
                                           uint32_t b_n, uint32_t b_k,
                                           float acch[4][4], float accl[4][4]) {
#pragma unroll
    for (int kk = 0; kk < 16; kk++) {
        uint32_t a[4];
        ldsm4(a, AB + ((mrow + a_row) * A_STR + kk * 16 + a_col) * 2);
        int kg = kg0 + kk * 16;
        uint32_t bh0[4], bh1[4], bl0[4], bl1[4];
        ldsm4(bh0, WHI + (b_n * W_STR + kg + b_k) * 2);
        ldsm4(bh1, WHI + ((16 + b_n) * W_STR + kg + b_k) * 2);
        ldsm4(bl0, WLO + (b_n * W_STR + kg + b_k) * 2);
        ldsm4(bl1, WLO + ((16 + b_n) * W_STR + kg + b_k) * 2);
        mma_f16(acch[0], a, bh0[0], bh0[1]);
        mma_f16(accl[0], a, bl0[0], bl0[1]);
        mma_f16(acch[1], a, bh0[2], bh0[3]);
        mma_f16(accl[1], a, bl0[2], bl0[3]);
        mma_f16(acch[2], a, bh1[0], bh1[1]);
        mma_f16(accl[2], a, bl1[0], bl1[1]);
        mma_f16(acch[3], a, bh1[2], bh1[3]);
        mma_f16(accl[3], a, bl1[2], bl1[3]);
    }
}

template<bool L0>
__global__ __launch_bounds__(256, 1) void scan_mma(
    const __half* __restrict__ xgf, const __half* __restrict__ xgr,
    const float* __restrict__ whhf, const float* __restrict__ whhr,
    const float* __restrict__ bhhf, const float* __restrict__ bhhr,
    __half* __restrict__ hrec, float* __restrict__ houtf,
    __half* __restrict__ houth, int* __restrict__ bar) {
    constexpr int MC = L0 ? 128 : 64;
    constexpr int ASZ = MC * A_STR * 2;
    extern __shared__ __align__(16) char smem[];
    const uint32_t sb  = smem_to_u32(smem);
    const uint32_t WHI = sb, WLO = sb + W_SPL_BYTES;
    const uint32_t AB0 = sb + SCAN_W_BYTES, AB1 = AB0 + ASZ;

    const int tid = threadIdx.x, lane = tid & 31, wid = tid >> 5;
    const int grp   = blockIdx.x >> 6;
    const int slice = blockIdx.x & 63;
    const int j0    = slice * 8;
    const int bbase = L0 ? 0 : grp * 64;
    const int bsub  = slice & 7;

    const float* whh = (L0 && grp) ? whhr : whhf;
    const float* bhh = (L0 && grp) ? bhhr : bhhf;
    const __half* xg = (L0 && grp) ? xgr  : xgf;
    int* barp = bar + grp * BAR_GRP;
    __half* hbuf = hrec + (L0 ? (size_t)grp * 2 * BB * HH : 0);

#pragma unroll
    for (int i = 0; i < 16; i++) {
        int idx = tid + i * 256;
        int n = idx >> 7, c4 = idx & 127;
        int grow = (n >> 3) * 512 + j0 + (n & 7);
        float4 v = *(const float4*)(whh + (size_t)grow * 512 + c4 * 4);
        uint32_t off = (n * W_STR + c4 * 4) * 2;
        splitw_store(WHI + off, WLO + off, v);
    }
    __syncthreads();

    const uint32_t a_row = lane & 15;
    const uint32_t a_col = (lane >> 4) << 3;
    const uint32_t b_n   = (lane & 7) + ((lane >> 4) << 3);
    const uint32_t b_k   = ((lane >> 3) & 1) << 3;
    const int r = lane >> 2;
    const int u = (lane & 3) * 2;
    const int wm = L0 ? wid : (wid & 3);
    const int mrow = wm * 16;
    const bool owner = L0 || (wid < 4);

    float bias[4][2];
#pragma unroll
    for (int g = 0; g < 4; g++) {
        bias[g][0] = bhh[g * 512 + j0 + u];
        bias[g][1] = bhh[g * 512 + j0 + u + 1];
    }
    float c[4] = {0.f, 0.f, 0.f, 0.f};

    uint32_t xrn[4][2];
    if (owner) {
        const int t0 = (L0 && grp) ? (TT - 1) : 0;
        const __half* xp = xg + ((size_t)(t0 * BB + bbase + mrow + r)) * G4H + j0 + u;
#pragma unroll
        for (int g = 0; g < 4; g++)
#pragma unroll
            for (int rp = 0; rp < 2; rp++)
                xrn[g][rp] = *(const uint32_t*)(xp + (size_t)rp * 8 * G4H + g * 512);
    }

    for (int step = 0; step < TT; step++) {
        const int t = (L0 && grp) ? (TT - 1 - step) : step;

        uint32_t xr[4][2];
#pragma unroll
        for (int g = 0; g < 4; g++)
#pragma unroll
            for (int rp = 0; rp < 2; rp++) xr[g][rp] = xrn[g][rp];

        float acch[4][4], accl[4][4];
#pragma unroll
        for (int g = 0; g < 4; g++)
#pragma unroll
            for (int k = 0; k < 4; k++) { acch[g][k] = 0.f; accl[g][k] = 0.f; }

        if (step > 0) {
            const int rpar = (step - 1) & 1;
            const __half* hs = hbuf + (size_t)rpar * BB * HH;
            stage_chunk<MC>(AB0, hs, bbase, 0, tid);
            stage_chunk<MC>(AB1, hs, bbase, 256, tid);
            CP_COMMIT;
            CP_WAIT_0;
            __syncthreads();
            if (L0) {
                mma_chunk2(AB0, WHI, WLO, mrow, 0, a_row, a_col, b_n, b_k, acch, accl);
                mma_chunk2(AB1, WHI, WLO, mrow, 256, a_row, a_col, b_n, b_k, acch, accl);
            } else {
                const int ks = wid >> 2;
                mma_chunk2(ks ? AB1 : AB0, WHI, WLO, mrow, ks * 256,
                           a_row, a_col, b_n, b_k, acch, accl);
            }
        }

        float acc[4][4];
#pragma unroll
        for (int g = 0; g < 4; g++)
#pragma unroll
            for (int k = 0; k < 4; k++) acc[g][k] = acch[g][k] + accl[g][k];

        if (!L0) {
            __syncthreads();
            if (wid >= 4) {
                uint32_t base = AB0 + ((wid - 4) * 32 + lane) * 4;
#pragma unroll
                for (int f = 0; f < 16; f++)
                    *(float*)(smem + (base - sb) + f * 512) = acc[f >> 2][f & 3];
            }
            __syncthreads();
            if (wid < 4) {
                uint32_t base = AB0 + (wid * 32 + lane) * 4;
#pragma unroll
                for (int f = 0; f < 16; f++)
                    acc[f >> 2][f & 3] += *(float*)(smem + (base - sb) + f * 512);
            }
        }

        if (owner) {
            const int wpar = step & 1;
            __half* dh = hbuf + (size_t)wpar * BB * HH;
#pragma unroll
            for (int rp = 0; rp < 2; rp++) {
                const int b = bbase + mrow + r + rp * 8;
                float hv2[2];
#pragma unroll
                for (int cc = 0; cc < 2; cc++) {
                    const int k = rp * 2 + cc;
                    float2 x0 = __half22float2(*(__half2*)&xr[0][rp]);
                    float2 x1 = __half22float2(*(__half2*)&xr[1][rp]);
                    float2 x2 = __half22float2(*(__half2*)&xr[2][rp]);
                    float2 x3 = __half22float2(*(__half2*)&xr[3][rp]);
                    float gi = acc[0][k] + (cc ? x0.y : x0.x) + bias[0][cc];
                    float gf = acc[1][k] + (cc ? x1.y : x1.x) + bias[1][cc];
                    float gg = acc[2][k] + (cc ? x2.y : x2.x) + bias[2][cc];
                    float go = acc[3][k] + (cc ? x3.y : x3.x) + bias[3][cc];
                    float cv = sigmoidf_(gf) * c[k] + sigmoidf_(gi) * tanhf(gg);
                    c[k] = cv;
                    hv2[cc] = sigmoidf_(go) * tanhf(cv);
                }
                if (L0) {
                    *(uint32_t*)(houth + ((size_t)(t * BB + b)) * 1024 + grp * 512 + j0 + u) =
                        pack_h2(hv2[0], hv2[1]);
                } else if (t == TT - 1) {
                    *(float2*)(houtf + (size_t)b * HH + j0 + u) =
                        make_float2(hv2[0], hv2[1]);
                }
                *(uint32_t*)(dh + (size_t)b * HH + j0 + u) = pack_h2(hv2[0], hv2[1]);
            }
        }

        if (step < TT - 1) {
            if (owner) {
                const int tn = (L0 && grp) ? (TT - 2 - step) : (step + 1);
                const __half* xp = xg + ((size_t)(tn * BB + bbase + mrow + r)) * G4H + j0 + u;
#pragma unroll
                for (int g = 0; g < 4; g++)
#pragma unroll
                    for (int rp = 0; rp < 2; rp++)
                        xrn[g][rp] = *(const uint32_t*)(xp + (size_t)rp * 8 * G4H + g * 512);
            }
            __threadfence();
            __syncthreads();
            if (tid == 0)
                bar_arrive_wait(barp + step * BAR_STEP, bsub, 64);
            __syncthreads();
        }
    }
}

// ========================= layer-1 reverse at t = T-1 ========================
__global__ void hr_last_kernel(const __half* __restrict__ xg,
                               const float* __restrict__ bhh,
                               float* __restrict__ hr) {
    int idx = blockIdx.x * blockDim.x + threadIdx.x;
    if (idx >= BB * HH) return;
    int b = idx >> 9, j = idx & 511;
    float gi = __half2float(xg[(size_t)b * G4H + j])        + bhh[j];
    float gg = __half2float(xg[(size_t)b * G4H + 1024 + j]) + bhh[1024 + j];
    float go = __half2float(xg[(size_t)b * G4H + 1536 + j]) + bhh[1536 + j];
    float cv = sigmoidf_(gi) * tanhf(gg);
    hr[idx] = sigmoidf_(go) * tanhf(cv);
}

// ========================= final projection ==================================
__global__ void out_kernel(const float* __restrict__ hf, const float* __restrict__ hr,
                           const float* __restrict__ wout, const float* __restrict__ bout,
                           float* __restrict__ out) {
    int b = blockIdx.x;
    int warp = threadIdx.x >> 5;
    int lane = threadIdx.x & 31;
    float s = 0.f;
    for (int k = lane; k < 512; k += 32) s += hf[(size_t)b * HH + k] * wout[warp * 1024 + k];
    for (int k = lane; k < 512; k += 32) s += hr[(size_t)b * HH + k] * wout[warp * 1024 + 512 + k];
#pragma unroll
    for (int off = 16; off; off >>= 1) s += __shfl_xor_sync(0xffffffffu, s, off);
    if (lane == 0) out[b * NCLS + warp] = s + bout[warp];
}

// ========================= host launch =======================================
extern "C" void kernel_launch(void* const* d_in, const int* in_sizes, int n_in,
                              void* d_out, int out_size) {
    const int*   x     = (const int*)  d_in[0];
    const float* emb   = (const float*)d_in[1];
    const float* wih0f = (const float*)d_in[2];
    const float* whh0f = (const float*)d_in[3];
    const float* bih0f = (const float*)d_in[4];
    const float* bhh0f = (const float*)d_in[5];
    const float* wih0r = (const float*)d_in[6];
    const float* whh0r = (const float*)d_in[7];
    const float* bih0r = (const float*)d_in[8];
    const float* bhh0r = (const float*)d_in[9];
    const float* wih1f = (const float*)d_in[10];
    const float* whh1f = (const float*)d_in[11];
    const float* bih1f = (const float*)d_in[12];
    const float* bhh1f = (const float*)d_in[13];
    const float* wih1r = (const float*)d_in[14];
    const float* whh1r = (const float*)d_in[15]; (void)whh1r;
    const float* bih1r = (const float*)d_in[16];
    const float* bhh1r = (const float*)d_in[17];
    const float* wout  = (const float*)d_in[18];
    const float* bout  = (const float*)d_in[19];
    float* out = (float*)d_out;

    __half *p_x0, *p_h0, *p_hf0, *p_hf1, *p_xg0f, *p_xg0r, *p_xg1f, *p_xg1r;
    float *p_h1f, *p_hr1;
    int *p_bar0, *p_bar1;
    cudaGetSymbolAddress((void**)&p_x0,   g_x0);
    cudaGetSymbolAddress((void**)&p_xg0f, g_xg0f);
    cudaGetSymbolAddress((void**)&p_xg0r, g_xg0r);
    cudaGetSymbolAddress((void**)&p_h0,   g_h0);
    cudaGetSymbolAddress((void**)&p_xg1f, g_xg1f);
    cudaGetSymbolAddress((void**)&p_xg1r, g_xg1r);
    cudaGetSymbolAddress((void**)&p_hf0,  g_hf0);
    cudaGetSymbolAddress((void**)&p_hf1,  g_hf1);
    cudaGetSymbolAddress((void**)&p_h1f,  g_h1f);
    cudaGetSymbolAddress((void**)&p_hr1,  g_hr1);
    cudaGetSymbolAddress((void**)&p_bar0, g_bar0);
    cudaGetSymbolAddress((void**)&p_bar1, g_bar1);

    cudaFuncSetAttribute(scan_mma<true>,  cudaFuncAttributeMaxDynamicSharedMemorySize, SCAN0_SMEM);
    cudaFuncSetAttribute(scan_mma<false>, cudaFuncAttributeMaxDynamicSharedMemorySize, SCAN1_SMEM);

    reset_kernel<<<128, 256>>>();
    embed_kernel<<<(TT * BB * (DEMB / 4) + 255) / 256, 256>>>(x, emb, p_x0);

    dim3 gBig(G4H / 128, (TT * BB) / 128);   // (16, 256)
    gemm_mma<<<gBig, 256>>>(p_x0, wih0f, bih0f, p_xg0f, TT * BB, G4H, DEMB);
    gemm_mma<<<gBig, 256>>>(p_x0, wih0r, bih0r, p_xg0r, TT * BB, G4H, DEMB);

    scan_mma<true><<<128, 256, SCAN0_SMEM>>>(p_xg0f, p_xg0r, whh0f, whh0r,
                                             bhh0f, bhh0r, p_hf0, nullptr,
                                             p_h0, p_bar0);

    gemm_mma<<<gBig, 256>>>(p_h0, wih1f, bih1f, p_xg1f, TT * BB, G4H, 2 * HH);
    gemm_mma<<<dim3(G4H / 128, 1), 256>>>(
        p_h0 + (size_t)(TT - 1) * BB * 1024, wih1r, bih1r, p_xg1r, BB, G4H, 2 * HH);

    scan_mma<false><<<128, 256, SCAN1_SMEM>>>(p_xg1f, p_xg1f, whh1f, whh1f,
                                              bhh1f, bhh1f, p_hf1, p_h1f,
                                              nullptr, p_bar1);

    hr_last_kernel<<<(BB * HH) / 256, 256>>>(p_xg1r, bhh1r, p_hr1);

    out_kernel<<<BB, 160>>>(p_h1f, p_hr1, wout, bout, out);
}

// round 14
// speedup vs baseline: 1.0481x; 1.0481x over previous
#include <cuda_runtime.h>
#include <cuda_fp16.h>
#include <math.h>
#include <cstdint>

#define TT 256
#define BB 128
#define HH 512
#define DEMB 256
#define PAD_IDX 29999
#define NCLS 5
#define G4H 2048  // 4*HH

#define BAR_SUB 8
#define BAR_SPC 32
#define BAR_STEP (BAR_SUB * BAR_SPC)
#define BAR_GRP  (TT * BAR_STEP)

__device__ __forceinline__ uint32_t smem_to_u32(const void* p) {
    uint32_t a;
    asm("{ .reg .u64 t; cvta.to.shared.u64 t, %1; cvt.u32.u64 %0, t; }" : "=r"(a) : "l"(p));
    return a;
}
#define CP_ASYNC16(dst, src) \
    asm volatile("cp.async.cg.shared.global [%0], [%1], 16;" :: "r"(dst), "l"(src))
#define CP_COMMIT  asm volatile("cp.async.commit_group;" ::: "memory")
#define CP_WAIT_1  asm volatile("cp.async.wait_group 1;" ::: "memory")
#define CP_WAIT_0  asm volatile("cp.async.wait_group 0;" ::: "memory")

// ========================= scratch (static, no allocs) =======================
__device__ __half g_x0 [(size_t)TT * BB * DEMB];
__device__ __half g_xg0f[(size_t)TT * BB * G4H];
__device__ __half g_xg0r[(size_t)TT * BB * G4H];
__device__ __half g_h0 [(size_t)TT * BB * 2 * HH];
__device__ __half g_xg1f[(size_t)TT * BB * G4H];
__device__ __half g_xg1r[(size_t)BB * G4H];
__device__ __half g_hf0[2 * 2 * BB * HH];
__device__ __half g_hf1[2 * BB * HH];
__device__ float g_h1f [BB * HH];
__device__ float g_hr1 [BB * HH];
__device__ int g_bar0[2 * BAR_GRP];
__device__ int g_bar1[2 * BAR_GRP];

__global__ void reset_kernel() {
    int n = 2 * BAR_GRP;
    for (int i = blockIdx.x * blockDim.x + threadIdx.x; i < n;
         i += gridDim.x * blockDim.x) {
        g_bar0[i] = 0;
        g_bar1[i] = 0;
    }
}

__device__ __forceinline__ uint32_t pack_h2(float a, float b) {
    __half2 h = __floats2half2_rn(a, b);
    return *(uint32_t*)&h;
}

__device__ __forceinline__ void bar_arrive_wait(int* base, int sub, int target) {
    atomicAdd(base + sub * BAR_SPC, 1);
    for (;;) {
        int sum = 0;
#pragma unroll
        for (int s = 0; s < BAR_SUB; s++) {
            int v;
            asm volatile("ld.global.cg.b32 %0, [%1];" : "=r"(v)
                         : "l"(base + s * BAR_SPC));
            sum += v;
        }
        if (sum >= target) break;
        __nanosleep(32);
    }
}

// ========================= embedding gather (fp16 out) =======================
__global__ void embed_kernel(const int* __restrict__ x,
                             const float* __restrict__ emb,
                             __half* __restrict__ out) {
    int gid = blockIdx.x * blockDim.x + threadIdx.x;
    if (gid >= TT * BB * (DEMB / 4)) return;
    int i4  = gid & 63;
    int row = gid >> 6;
    int t = row / BB;
    int b = row - t * BB;
    int xi = x[b * TT + t];
    float4 v;
    if (xi == PAD_IDX) { v.x = v.y = v.z = v.w = 0.f; }
    else               { v = ((const float4*)emb)[(size_t)xi * 64 + i4]; }
    uint2 p;
    p.x = pack_h2(v.x, v.y);
    p.y = pack_h2(v.z, v.w);
    ((uint2*)out)[gid] = p;
}

// ========================= mma primitives ====================================
__device__ __forceinline__ void ldsm4(uint32_t* r, uint32_t addr) {
    asm volatile("ldmatrix.sync.aligned.m8n8.x4.shared.b16 {%0,%1,%2,%3}, [%4];"
        : "=r"(r[0]), "=r"(r[1]), "=r"(r[2]), "=r"(r[3]) : "r"(addr));
}
__device__ __forceinline__ void mma_f16(float* d, const uint32_t* a,
                                        uint32_t b0, uint32_t b1) {
    asm volatile("mma.sync.aligned.m16n8k16.row.col.f32.f16.f16.f32 "
        "{%0,%1,%2,%3}, {%4,%5,%6,%7}, {%8,%9}, {%0,%1,%2,%3};"
        : "+f"(d[0]), "+f"(d[1]), "+f"(d[2]), "+f"(d[3])
        : "r"(a[0]), "r"(a[1]), "r"(a[2]), "r"(a[3]), "r"(b0), "r"(b1));
}
__device__ __forceinline__ void splitw_store(uint32_t hiA, uint32_t loA, float4 v) {
    __half h0 = __float2half_rn(v.x), h1 = __float2half_rn(v.y);
    __half h2 = __float2half_rn(v.z), h3 = __float2half_rn(v.w);
    float r0 = v.x - __half2float(h0), r1 = v.y - __half2float(h1);
    float r2 = v.z - __half2float(h2), r3 = v.w - __half2float(h3);
    uint32_t hp0 = pack_h2(__half2float(h0), __half2float(h1));
    uint32_t hp1 = pack_h2(__half2float(h2), __half2float(h3));
    uint32_t lp0 = pack_h2(r0, r1);
    uint32_t lp1 = pack_h2(r2, r3);
    asm volatile("st.shared.v2.b32 [%0], {%1, %2};" :: "r"(hiA), "r"(hp0), "r"(hp1) : "memory");
    asm volatile("st.shared.v2.b32 [%0], {%1, %2};" :: "r"(loA), "r"(lp0), "r"(lp1) : "memory");
}

// ========================= fp16-A GEMM: C(fp16) = A*W^T + bias ===============
#define KC  32
#define LDH 40
#define GA_BYTES (128 * LDH * 2)

__global__ __launch_bounds__(256, 2) void gemm_mma(const __half* __restrict__ A,
                                                   const float* __restrict__ W,
                                                   const float* __restrict__ bias,
                                                   __half* __restrict__ C,
                                                   int M, int N, int K) {
    __shared__ __align__(16) __half gsm[4 * 128 * LDH];
    const uint32_t sb  = smem_to_u32(gsm);
    const uint32_t AH0 = sb, AH1 = sb + GA_BYTES;
    const uint32_t BH  = sb + 2 * GA_BYTES, BL = BH + GA_BYTES;

    const int tid  = threadIdx.x;
    const int lane = tid & 31;
    const int wid  = tid >> 5;
    const int wm   = wid & 3;
    const int wn   = wid >> 2;
    const int bm   = blockIdx.y * 128;
    const int bn   = blockIdx.x * 128;

    float acc[2][8][4];
#pragma unroll
    for (int i = 0; i < 2; i++)
#pragma unroll
        for (int j = 0; j < 8; j++)
#pragma unroll
            for (int k = 0; k < 4; k++) acc[i][j][k] = 0.f;

    const uint32_t a_row = lane & 15;
    const uint32_t a_col = (lane >> 4) << 3;
    const uint32_t b_n   = (lane & 7) + ((lane >> 4) << 3);
    const uint32_t b_k   = ((lane >> 3) & 1) << 3;

    const int s_row = tid >> 2, s_c8 = tid & 3;
    const int w_row = tid >> 3, w_c4 = tid & 7;

    float4 vw[4];
#pragma unroll
    for (int i = 0; i < 2; i++) {
        int row = s_row + i * 64;
        CP_ASYNC16(AH0 + (row * LDH + s_c8 * 8) * 2,
                   A + (size_t)(bm + row) * K + s_c8 * 8);
    }
    CP_COMMIT;
#pragma unroll
    for (int i = 0; i < 4; i++) {
        int row = w_row + i * 32;
        vw[i] = *(const float4*)(W + (size_t)(bn + row) * K + w_c4 * 4);
    }

    const int nch = K / KC;
    for (int ch = 0; ch < nch; ch++) {
        const int kb = ch * KC;
        if (ch + 1 < nch) {
            uint32_t dst = ((ch + 1) & 1) ? AH1 : AH0;
#pragma unroll
            for (int i = 0; i < 2; i++) {
                int row = s_row + i * 64;
                CP_ASYNC16(dst + (row * LDH + s_c8 * 8) * 2,
                           A + (size_t)(bm + row) * K + kb + KC + s_c8 * 8);
            }
            CP_COMMIT;
        }
#pragma unroll
        for (int i = 0; i < 4; i++) {
            int row = w_row + i * 32;
            uint32_t off = (row * LDH + w_c4 * 4) * 2;
            splitw_store(BH + off, BL + off, vw[i]);
        }
        if (ch + 1 < nch) {
#pragma unroll
            for (int i = 0; i < 4; i++) {
                int row = w_row + i * 32;
                vw[i] = *(const float4*)(W + (size_t)(bn + row) * K + kb + KC + w_c4 * 4);
            }
        }
        if (ch + 1 < nch) { CP_WAIT_1; } else { CP_WAIT_0; }
        __syncthreads();

        const uint32_t AH = (ch & 1) ? AH1 : AH0;
#pragma unroll
        for (int ks = 0; ks < KC; ks += 16) {
            uint32_t ah[2][4];
#pragma unroll
            for (int ma = 0; ma < 2; ma++)
                ldsm4(ah[ma], AH + ((wm * 32 + ma * 16 + a_row) * LDH + ks + a_col) * 2);
#pragma unroll
            for (int bg = 0; bg < 4; bg++) {
                uint32_t boff = ((wn * 64 + bg * 16 + b_n) * LDH + ks + b_k) * 2;
                uint32_t bh[4], bl[4];
                ldsm4(bh, BH + boff);
                ldsm4(bl, BL + boff);
#pragma unroll
                for (int ma = 0; ma < 2; ma++) {
#pragma unroll
                    for (int na = 0; na < 2; na++) {
                        float* d = acc[ma][bg * 2 + na];
                        mma_f16(d, ah[ma], bh[na * 2], bh[na * 2 + 1]);
                        mma_f16(d, ah[ma], bl[na * 2], bl[na * 2 + 1]);
                    }
                }
            }
        }
        __syncthreads();
    }

#pragma unroll
    for (int ma = 0; ma < 2; ma++) {
        int row0 = bm + wm * 32 + ma * 16 + (lane >> 2);
#pragma unroll
        for (int na = 0; na < 8; na++) {
            int col = bn + wn * 64 + na * 8 + (lane & 3) * 2;
            float b0 = bias[col], b1 = bias[col + 1];
            *(uint32_t*)(C + (size_t)row0 * N + col) =
                pack_h2(acc[ma][na][0] + b0, acc[ma][na][1] + b1);
            *(uint32_t*)(C + (size_t)(row0 + 8) * N + col) =
                pack_h2(acc[ma][na][2] + b0, acc[ma][na][3] + b1);
        }
    }
}

__device__ __forceinline__ float sigmoidf_(float v) { return 1.f / (1.f + expf(-v)); }

// ========================= tensor-core LSTM scan =============================
#define W_STR 520
#define A_STR 264
#define W_SPL_BYTES (32 * W_STR * 2)
#define SCAN_W_BYTES (2 * W_SPL_BYTES)                    // 66560
#define SCAN0_SMEM (SCAN_W_BYTES + 2 * 128 * A_STR * 2)   // 201728
#define SCAN1_SMEM (SCAN_W_BYTES + 2 * 64 * A_STR * 2)    // 134144

template<int MC>
__device__ __forceinline__ void stage_chunk(uint32_t dst, const __half* hs,
                                            int bbase, int kb, int tid) {
#pragma unroll
    for (int i = 0; i < MC / 8; i++) {
        int e = tid + i * 256;
        int row = e >> 5, seg = e & 31;
        const __half* src = hs + (size_t)(bbase + row) * HH + kb + seg * 8;
        CP_ASYNC16(dst + (row * A_STR + seg * 8) * 2, src);
    }
}

// split hi/lo accumulators -> 8 independent HMMA chains per warp
__device__ __forceinline__ void mma_chunk2(uint32_t AB, uint32_t WHI, uint32_t WLO,
                                           int mrow, int kg0,
                                           uint32_t a_row, uint32_t a_col,
                                           uint32_t b_n, uint32_t b_k,
                                           float acch[4][4], float accl[4][4]) {
#pragma unroll
    for (int kk = 0; kk < 16; kk++) {
        uint32_t a[4];
        ldsm4(a, AB + ((mrow + a_row) * A_STR + kk * 16 + a_col) * 2);
        int kg = kg0 + kk * 16;
        uint32_t bh0[4], bh1[4], bl0[4], bl1[4];
        ldsm4(bh0, WHI + (b_n * W_STR + kg + b_k) * 2);
        ldsm4(bh1, WHI + ((16 + b_n) * W_STR + kg + b_k) * 2);
        ldsm4(bl0, WLO + (b_n * W_STR + kg + b_k) * 2);
        ldsm4(bl1, WLO + ((16 + b_n) * W_STR + kg + b_k) * 2);
        mma_f16(acch[0], a, bh0[0], bh0[1]);
        mma_f16(accl[0], a, bl0[0], bl0[1]);
        mma_f16(acch[1], a, bh0[2], bh0[3]);
        mma_f16(accl[1], a, bl0[2], bl0[3]);
        mma_f16(acch[2], a, bh1[0], bh1[1]);
        mma_f16(accl[2], a, bl1[0], bl1[1]);
        mma_f16(acch[3], a, bh1[2], bh1[3]);
        mma_f16(accl[3], a, bl1[2], bl1[3]);
    }
}

template<bool L0>
__global__ __launch_bounds__(256, 1) void scan_mma(
    const __half* __restrict__ xgf, const __half* __restrict__ xgr,
    const float* __restrict__ whhf, const float* __restrict__ whhr,
    const float* __restrict__ bhhf, const float* __restrict__ bhhr,
    __half* __restrict__ hrec, float* __restrict__ houtf,
    __half* __restrict__ houth, int* __restrict__ bar) {
    constexpr int MC = L0 ? 128 : 64;
    constexpr int ASZ = MC * A_STR * 2;
    extern __shared__ __align__(16) char smem[];
    const uint32_t sb  = smem_to_u32(smem);
    const uint32_t WHI = sb, WLO = sb + W_SPL_BYTES;
    const uint32_t AB0 = sb + SCAN_W_BYTES, AB1 = AB0 + ASZ;

    const int tid = threadIdx.x, lane = tid & 31, wid = tid >> 5;
    const int grp   = blockIdx.x >> 6;
    const int slice = blockIdx.x & 63;
    const int j0    = slice * 8;
    const int bbase = L0 ? 0 : grp * 64;
    const int bsub  = slice & 7;

    const float* whh = (L0 && grp) ? whhr : whhf;
    const float* bhh = (L0 && grp) ? bhhr : bhhf;
    const __half* xg = (L0 && grp) ? xgr  : xgf;
    int* barp = bar + grp * BAR_GRP;
    __half* hbuf = hrec + (L0 ? (size_t)grp * 2 * BB * HH : 0);

#pragma unroll
    for (int i = 0; i < 16; i++) {
        int idx = tid + i * 256;
        int n = idx >> 7, c4 = idx & 127;
        int grow = (n >> 3) * 512 + j0 + (n & 7);
        float4 v = *(const float4*)(whh + (size_t)grow * 512 + c4 * 4);
        uint32_t off = (n * W_STR + c4 * 4) * 2;
        splitw_store(WHI + off, WLO + off, v);
    }
    __syncthreads();

    const uint32_t a_row = lane & 15;
    const uint32_t a_col = (lane >> 4) << 3;
    const uint32_t b_n   = (lane & 7) + ((lane >> 4) << 3);
    const uint32_t b_k   = ((lane >> 3) & 1) << 3;
    const int r = lane >> 2;
    const int u = (lane & 3) * 2;
    const int wm = L0 ? wid : (wid & 3);
    const int mrow = wm * 16;
    const bool owner = L0 || (wid < 4);

    float bias[4][2];
#pragma unroll
    for (int g = 0; g < 4; g++) {
        bias[g][0] = bhh[g * 512 + j0 + u];
        bias[g][1] = bhh[g * 512 + j0 + u + 1];
    }
    float c[4] = {0.f, 0.f, 0.f, 0.f};

    uint32_t xrn[4][2];
    if (owner) {
        const int t0 = (L0 && grp) ? (TT - 1) : 0;
        const __half* xp = xg + ((size_t)(t0 * BB + bbase + mrow + r)) * G4H + j0 + u;
#pragma unroll
        for (int g = 0; g < 4; g++)
#pragma unroll
            for (int rp = 0; rp < 2; rp++)
                xrn[g][rp] = *(const uint32_t*)(xp + (size_t)rp * 8 * G4H + g * 512);
    }

    for (int step = 0; step < TT; step++) {
        const int t = (L0 && grp) ? (TT - 1 - step) : step;

        uint32_t xr[4][2];
#pragma unroll
        for (int g = 0; g < 4; g++)
#pragma unroll
            for (int rp = 0; rp < 2; rp++) xr[g][rp] = xrn[g][rp];

        float acch[4][4], accl[4][4];
#pragma unroll
        for (int g = 0; g < 4; g++)
#pragma unroll
            for (int k = 0; k < 4; k++) { acch[g][k] = 0.f; accl[g][k] = 0.f; }

        if (step > 0) {
            const int rpar = (step - 1) & 1;
            const __half* hs = hbuf + (size_t)rpar * BB * HH;
            stage_chunk<MC>(AB0, hs, bbase, 0, tid);   CP_COMMIT;
            stage_chunk<MC>(AB1, hs, bbase, 256, tid); CP_COMMIT;
            if (L0) {
                CP_WAIT_1;
                __syncthreads();
                mma_chunk2(AB0, WHI, WLO, mrow, 0, a_row, a_col, b_n, b_k, acch, accl);
                CP_WAIT_0;
                __syncthreads();
                mma_chunk2(AB1, WHI, WLO, mrow, 256, a_row, a_col, b_n, b_k, acch, accl);
            } else {
                CP_WAIT_0;
                __syncthreads();
                const int ks = wid >> 2;
                mma_chunk2(ks ? AB1 : AB0, WHI, WLO, mrow, ks * 256,
                           a_row, a_col, b_n, b_k, acch, accl);
            }
        }

        float acc[4][4];
#pragma unroll
        for (int g = 0; g < 4; g++)
#pragma unroll
            for (int k = 0; k < 4; k++) acc[g][k] = acch[g][k] + accl[g][k];

        if (!L0) {
            __syncthreads();
            if (wid >= 4) {
                uint32_t base = AB0 + ((wid - 4) * 32 + lane) * 4;
#pragma unroll
                for (int f = 0; f < 16; f++)
                    *(float*)(smem + (base - sb) + f * 512) = acc[f >> 2][f & 3];
            }
            __syncthreads();
            if (wid < 4) {
                uint32_t base = AB0 + (wid * 32 + lane) * 4;
#pragma unroll
                for (int f = 0; f < 16; f++)
                    acc[f >> 2][f & 3] += *(float*)(smem + (base - sb) + f * 512);
            }
        }

        if (owner) {
            const int wpar = step & 1;
            __half* dh = hbuf + (size_t)wpar * BB * HH;
#pragma unroll
            for (int rp = 0; rp < 2; rp++) {
                const int b = bbase + mrow + r + rp * 8;
                float hv2[2];
#pragma unroll
                for (int cc = 0; cc < 2; cc++) {
                    const int k = rp * 2 + cc;
                    float2 x0 = __half22float2(*(__half2*)&xr[0][rp]);
                    float2 x1 = __half22float2(*(__half2*)&xr[1][rp]);
                    float2 x2 = __half22float2(*(__half2*)&xr[2][rp]);
                    float2 x3 = __half22float2(*(__half2*)&xr[3][rp]);
                    float gi = acc[0][k] + (cc ? x0.y : x0.x) + bias[0][cc];
                    float gf = acc[1][k] + (cc ? x1.y : x1.x) + bias[1][cc];
                    float gg = acc[2][k] + (cc ? x2.y : x2.x) + bias[2][cc];
                    float go = acc[3][k] + (cc ? x3.y : x3.x) + bias[3][cc];
                    float cv = sigmoidf_(gf) * c[k] + sigmoidf_(gi) * tanhf(gg);
                    c[k] = cv;
                    hv2[cc] = sigmoidf_(go) * tanhf(cv);
                }
                if (L0) {
                    *(uint32_t*)(houth + ((size_t)(t * BB + b)) * 1024 + grp * 512 + j0 + u) =
                        pack_h2(hv2[0], hv2[1]);
                } else if (t == TT - 1) {
                    *(float2*)(houtf + (size_t)b * HH + j0 + u) =
                        make_float2(hv2[0], hv2[1]);
                }
                *(uint32_t*)(dh + (size_t)b * HH + j0 + u) = pack_h2(hv2[0], hv2[1]);
            }
        }

        if (step < TT - 1) {
            if (owner) {
                const int tn = (L0 && grp) ? (TT - 2 - step) : (step + 1);
                const __half* xp = xg + ((size_t)(tn * BB + bbase + mrow + r)) * G4H + j0 + u;
#pragma unroll
                for (int g = 0; g < 4; g++)
#pragma unroll
                    for (int rp = 0; rp < 2; rp++)
                        xrn[g][rp] = *(const uint32_t*)(xp + (size_t)rp * 8 * G4H + g * 512);
            }
            __threadfence();
            __syncthreads();
            if (tid == 0)
                bar_arrive_wait(barp + step * BAR_STEP, bsub, 64);
            __syncthreads();
        }
    }
}

// ========================= layer-1 reverse at t = T-1 ========================
__global__ void hr_last_kernel(const __half* __restrict__ xg,
                               const float* __restrict__ bhh,
                               float* __restrict__ hr) {
    int idx = blockIdx.x * blockDim.x + threadIdx.x;
    if (idx >= BB * HH) return;
    int b = idx >> 9, j = idx & 511;
    float gi = __half2float(xg[(size_t)b * G4H + j])        + bhh[j];
    float gg = __half2float(xg[(size_t)b * G4H + 1024 + j]) + bhh[1024 + j];
    float go = __half2float(xg[(size_t)b * G4H + 1536 + j]) + bhh[1536 + j];
    float cv = sigmoidf_(gi) * tanhf(gg);
    hr[idx] = sigmoidf_(go) * tanhf(cv);
}

// ========================= final projection ==================================
__global__ void out_kernel(const float* __restrict__ hf, const float* __restrict__ hr,
                           const float* __restrict__ wout, const float* __restrict__ bout,
                           float* __restrict__ out) {
    int b = blockIdx.x;
    int warp = threadIdx.x >> 5;
    int lane = threadIdx.x & 31;
    float s = 0.f;
    for (int k = lane; k < 512; k += 32) s += hf[(size_t)b * HH + k] * wout[warp * 1024 + k];
    for (int k = lane; k < 512; k += 32) s += hr[(size_t)b * HH + k] * wout[warp * 1024 + 512 + k];
#pragma unroll
    for (int off = 16; off; off >>= 1) s += __shfl_xor_sync(0xffffffffu, s, off);
    if (lane == 0) out[b * NCLS + warp] = s + bout[warp];
}

// ========================= host launch =======================================
extern "C" void kernel_launch(void* const* d_in, const int* in_sizes, int n_in,
                              void* d_out, int out_size) {
    const int*   x     = (const int*)  d_in[0];
    const float* emb   = (const float*)d_in[1];
    const float* wih0f = (const float*)d_in[2];
    const float* whh0f = (const float*)d_in[3];
    const float* bih0f = (const float*)d_in[4];
    const float* bhh0f = (const float*)d_in[5];
    const float* wih0r = (const float*)d_in[6];
    const float* whh0r = (const float*)d_in[7];
    const float* bih0r = (const float*)d_in[8];
    const float* bhh0r = (const float*)d_in[9];
    const float* wih1f = (const float*)d_in[10];
    const float* whh1f = (const float*)d_in[11];
    const float* bih1f = (const float*)d_in[12];
    const float* bhh1f = (const float*)d_in[13];
    const float* wih1r = (const float*)d_in[14];
    const float* whh1r = (const float*)d_in[15]; (void)whh1r;
    const float* bih1r = (const float*)d_in[16];
    const float* bhh1r = (const float*)d_in[17];
    const float* wout  = (const float*)d_in[18];
    const float* bout  = (const float*)d_in[19];
    float* out = (float*)d_out;

    __half *p_x0, *p_h0, *p_hf0, *p_hf1, *p_xg0f, *p_xg0r, *p_xg1f, *p_xg1r;
    float *p_h1f, *p_hr1;
    int *p_bar0, *p_bar1;
    cudaGetSymbolAddress((void**)&p_x0,   g_x0);
    cudaGetSymbolAddress((void**)&p_xg0f, g_xg0f);
    cudaGetSymbolAddress((void**)&p_xg0r, g_xg0r);
    cudaGetSymbolAddress((void**)&p_h0,   g_h0);
    cudaGetSymbolAddress((void**)&p_xg1f, g_xg1f);
    cudaGetSymbolAddress((void**)&p_xg1r, g_xg1r);
    cudaGetSymbolAddress((void**)&p_hf0,  g_hf0);
    cudaGetSymbolAddress((void**)&p_hf1,  g_hf1);
    cudaGetSymbolAddress((void**)&p_h1f,  g_h1f);
    cudaGetSymbolAddress((void**)&p_hr1,  g_hr1);
    cudaGetSymbolAddress((void**)&p_bar0, g_bar0);
    cudaGetSymbolAddress((void**)&p_bar1, g_bar1);

    cudaFuncSetAttribute(scan_mma<true>,  cudaFuncAttributeMaxDynamicSharedMemorySize, SCAN0_SMEM);
    cudaFuncSetAttribute(scan_mma<false>, cudaFuncAttributeMaxDynamicSharedMemorySize, SCAN1_SMEM);

    reset_kernel<<<128, 256>>>();
    embed_kernel<<<(TT * BB * (DEMB / 4) + 255) / 256, 256>>>(x, emb, p_x0);

    dim3 gBig(G4H / 128, (TT * BB) / 128);   // (16, 256)
    gemm_mma<<<gBig, 256>>>(p_x0, wih0f, bih0f, p_xg0f, TT * BB, G4H, DEMB);
    gemm_mma<<<gBig, 256>>>(p_x0, wih0r, bih0r, p_xg0r, TT * BB, G4H, DEMB);

    scan_mma<true><<<128, 256, SCAN0_SMEM>>>(p_xg0f, p_xg0r, whh0f, whh0r,
                                             bhh0f, bhh0r, p_hf0, nullptr,
                                             p_h0, p_bar0);

    gemm_mma<<<gBig, 256>>>(p_h0, wih1f, bih1f, p_xg1f, TT * BB, G4H, 2 * HH);
    gemm_mma<<<dim3(G4H / 128, 1), 256>>>(
        p_h0 + (size_t)(TT - 1) * BB * 1024, wih1r, bih1r, p_xg1r, BB, G4H, 2 * HH);

    scan_mma<false><<<128, 256, SCAN1_SMEM>>>(p_xg1f, p_xg1f, whh1f, whh1f,
                                              bhh1f, bhh1f, p_hf1, p_h1f,
                                              nullptr, p_bar1);

    hr_last_kernel<<<(BB * HH) / 256, 256>>>(p_xg1r, bhh1r, p_hr1);

    out_kernel<<<BB, 160>>>(p_h1f, p_hr1, wout, bout, out);
}

// round 15
// speedup vs baseline: 1.1961x; 1.1412x over previous
#include <cuda_runtime.h>
#include <cuda_fp16.h>
#include <math.h>
#include <cstdint>

#define TT 256
#define BB 128
#define HH 512
#define DEMB 256
#define PAD_IDX 29999
#define NCLS 5
#define G4H 2048  // 4*HH

#define BAR_SUB 8
#define BAR_SPC 32
#define BAR_STEP (BAR_SUB * BAR_SPC)
#define BAR_GRP  (TT * BAR_STEP)

__device__ __forceinline__ uint32_t smem_to_u32(const void* p) {
    uint32_t a;
    asm("{ .reg .u64 t; cvta.to.shared.u64 t, %1; cvt.u32.u64 %0, t; }" : "=r"(a) : "l"(p));
    return a;
}
#define CP_ASYNC16(dst, src) \
    asm volatile("cp.async.cg.shared.global [%0], [%1], 16;" :: "r"(dst), "l"(src))
#define CP_COMMIT  asm volatile("cp.async.commit_group;" ::: "memory")
#define CP_WAIT_1  asm volatile("cp.async.wait_group 1;" ::: "memory")
#define CP_WAIT_0  asm volatile("cp.async.wait_group 0;" ::: "memory")

// ========================= scratch (static, no allocs) =======================
__device__ __half g_x0 [(size_t)TT * BB * DEMB];
__device__ __half g_xg0f[(size_t)TT * BB * G4H];
__device__ __half g_xg0r[(size_t)TT * BB * G4H];
__device__ __half g_h0 [(size_t)TT * BB * 2 * HH];
__device__ __half g_xg1f[(size_t)TT * BB * G4H];
__device__ __half g_xg1r[(size_t)BB * G4H];
__device__ __half g_hf0[2 * 2 * BB * HH];
__device__ __half g_hf1[2 * BB * HH];
__device__ float g_h1f [BB * HH];
__device__ float g_hr1 [BB * HH];
__device__ int g_bar0[2 * BAR_GRP];
__device__ int g_bar1[2 * BAR_GRP];

__global__ void reset_kernel() {
    int n = 2 * BAR_GRP;
    for (int i = blockIdx.x * blockDim.x + threadIdx.x; i < n;
         i += gridDim.x * blockDim.x) {
        g_bar0[i] = 0;
        g_bar1[i] = 0;
    }
}

__device__ __forceinline__ uint32_t pack_h2(float a, float b) {
    __half2 h = __floats2half2_rn(a, b);
    return *(uint32_t*)&h;
}

__device__ __forceinline__ void bar_arrive_wait(int* base, int sub, int target) {
    atomicAdd(base + sub * BAR_SPC, 1);
    for (;;) {
        int sum = 0;
#pragma unroll
        for (int s = 0; s < BAR_SUB; s++) {
            int v;
            asm volatile("ld.global.cg.b32 %0, [%1];" : "=r"(v)
                         : "l"(base + s * BAR_SPC));
            sum += v;
        }
        if (sum >= target) break;
        __nanosleep(32);
    }
}

// ========================= embedding gather (fp16 out) =======================
__global__ void embed_kernel(const int* __restrict__ x,
                             const float* __restrict__ emb,
                             __half* __restrict__ out) {
    int gid = blockIdx.x * blockDim.x + threadIdx.x;
    if (gid >= TT * BB * (DEMB / 4)) return;
    int i4  = gid & 63;
    int row = gid >> 6;
    int t = row / BB;
    int b = row - t * BB;
    int xi = x[b * TT + t];
    float4 v;
    if (xi == PAD_IDX) { v.x = v.y = v.z = v.w = 0.f; }
    else               { v = ((const float4*)emb)[(size_t)xi * 64 + i4]; }
    uint2 p;
    p.x = pack_h2(v.x, v.y);
    p.y = pack_h2(v.z, v.w);
    ((uint2*)out)[gid] = p;
}

// ========================= mma primitives ====================================
__device__ __forceinline__ void ldsm4(uint32_t* r, uint32_t addr) {
    asm volatile("ldmatrix.sync.aligned.m8n8.x4.shared.b16 {%0,%1,%2,%3}, [%4];"
        : "=r"(r[0]), "=r"(r[1]), "=r"(r[2]), "=r"(r[3]) : "r"(addr));
}
__device__ __forceinline__ void mma_f16(float* d, const uint32_t* a,
                                        uint32_t b0, uint32_t b1) {
    asm volatile("mma.sync.aligned.m16n8k16.row.col.f32.f16.f16.f32 "
        "{%0,%1,%2,%3}, {%4,%5,%6,%7}, {%8,%9}, {%0,%1,%2,%3};"
        : "+f"(d[0]), "+f"(d[1]), "+f"(d[2]), "+f"(d[3])
        : "r"(a[0]), "r"(a[1]), "r"(a[2]), "r"(a[3]), "r"(b0), "r"(b1));
}
__device__ __forceinline__ void splitw_store(uint32_t hiA, uint32_t loA, float4 v) {
    __half h0 = __float2half_rn(v.x), h1 = __float2half_rn(v.y);
    __half h2 = __float2half_rn(v.z), h3 = __float2half_rn(v.w);
    float r0 = v.x - __half2float(h0), r1 = v.y - __half2float(h1);
    float r2 = v.z - __half2float(h2), r3 = v.w - __half2float(h3);
    uint32_t hp0 = pack_h2(__half2float(h0), __half2float(h1));
    uint32_t hp1 = pack_h2(__half2float(h2), __half2float(h3));
    uint32_t lp0 = pack_h2(r0, r1);
    uint32_t lp1 = pack_h2(r2, r3);
    asm volatile("st.shared.v2.b32 [%0], {%1, %2};" :: "r"(hiA), "r"(hp0), "r"(hp1) : "memory");
    asm volatile("st.shared.v2.b32 [%0], {%1, %2};" :: "r"(loA), "r"(lp0), "r"(lp1) : "memory");
}
__device__ __forceinline__ void wh_store(uint32_t hiA, float4 v) {
    uint32_t hp0 = pack_h2(v.x, v.y);
    uint32_t hp1 = pack_h2(v.z, v.w);
    asm volatile("st.shared.v2.b32 [%0], {%1, %2};" :: "r"(hiA), "r"(hp0), "r"(hp1) : "memory");
}

// ========================= fp16-A GEMM: C(fp16) = A*W^T + bias ===============
#define KC  32
#define LDH 40
#define GA_BYTES (128 * LDH * 2)

__global__ __launch_bounds__(256, 2) void gemm_mma(const __half* __restrict__ A,
                                                   const float* __restrict__ W,
                                                   const float* __restrict__ bias,
                                                   __half* __restrict__ C,
                                                   int M, int N, int K) {
    __shared__ __align__(16) __half gsm[4 * 128 * LDH];
    const uint32_t sb  = smem_to_u32(gsm);
    const uint32_t AH0 = sb, AH1 = sb + GA_BYTES;
    const uint32_t BH  = sb + 2 * GA_BYTES, BL = BH + GA_BYTES;

    const int tid  = threadIdx.x;
    const int lane = tid & 31;
    const int wid  = tid >> 5;
    const int wm   = wid & 3;
    const int wn   = wid >> 2;
    const int bm   = blockIdx.y * 128;
    const int bn   = blockIdx.x * 128;

    float acc[2][8][4];
#pragma unroll
    for (int i = 0; i < 2; i++)
#pragma unroll
        for (int j = 0; j < 8; j++)
#pragma unroll
            for (int k = 0; k < 4; k++) acc[i][j][k] = 0.f;

    const uint32_t a_row = lane & 15;
    const uint32_t a_col = (lane >> 4) << 3;
    const uint32_t b_n   = (lane & 7) + ((lane >> 4) << 3);
    const uint32_t b_k   = ((lane >> 3) & 1) << 3;

    const int s_row = tid >> 2, s_c8 = tid & 3;
    const int w_row = tid >> 3, w_c4 = tid & 7;

    float4 vw[4];
#pragma unroll
    for (int i = 0; i < 2; i++) {
        int row = s_row + i * 64;
        CP_ASYNC16(AH0 + (row * LDH + s_c8 * 8) * 2,
                   A + (size_t)(bm + row) * K + s_c8 * 8);
    }
    CP_COMMIT;
#pragma unroll
    for (int i = 0; i < 4; i++) {
        int row = w_row + i * 32;
        vw[i] = *(const float4*)(W + (size_t)(bn + row) * K + w_c4 * 4);
    }

    const int nch = K / KC;
    for (int ch = 0; ch < nch; ch++) {
        const int kb = ch * KC;
        if (ch + 1 < nch) {
            uint32_t dst = ((ch + 1) & 1) ? AH1 : AH0;
#pragma unroll
            for (int i = 0; i < 2; i++) {
                int row = s_row + i * 64;
                CP_ASYNC16(dst + (row * LDH + s_c8 * 8) * 2,
                           A + (size_t)(bm + row) * K + kb + KC + s_c8 * 8);
            }
            CP_COMMIT;
        }
#pragma unroll
        for (int i = 0; i < 4; i++) {
            int row = w_row + i * 32;
            uint32_t off = (row * LDH + w_c4 * 4) * 2;
            splitw_store(BH + off, BL + off, vw[i]);
        }
        if (ch + 1 < nch) {
#pragma unroll
            for (int i = 0; i < 4; i++) {
                int row = w_row + i * 32;
                vw[i] = *(const float4*)(W + (size_t)(bn + row) * K + kb + KC + w_c4 * 4);
            }
        }
        if (ch + 1 < nch) { CP_WAIT_1; } else { CP_WAIT_0; }
        __syncthreads();

        const uint32_t AH = (ch & 1) ? AH1 : AH0;
#pragma unroll
        for (int ks = 0; ks < KC; ks += 16) {
            uint32_t ah[2][4];
#pragma unroll
            for (int ma = 0; ma < 2; ma++)
                ldsm4(ah[ma], AH + ((wm * 32 + ma * 16 + a_row) * LDH + ks + a_col) * 2);
#pragma unroll
            for (int bg = 0; bg < 4; bg++) {
                uint32_t boff = ((wn * 64 + bg * 16 + b_n) * LDH + ks + b_k) * 2;
                uint32_t bh[4], bl[4];
                ldsm4(bh, BH + boff);
                ldsm4(bl, BL + boff);
#pragma unroll
                for (int ma = 0; ma < 2; ma++) {
#pragma unroll
                    for (int na = 0; na < 2; na++) {
                        float* d = acc[ma][bg * 2 + na];
                        mma_f16(d, ah[ma], bh[na * 2], bh[na * 2 + 1]);
                        mma_f16(d, ah[ma], bl[na * 2], bl[na * 2 + 1]);
                    }
                }
            }
        }
        __syncthreads();
    }

#pragma unroll
    for (int ma = 0; ma < 2; ma++) {
        int row0 = bm + wm * 32 + ma * 16 + (lane >> 2);
#pragma unroll
        for (int na = 0; na < 8; na++) {
            int col = bn + wn * 64 + na * 8 + (lane & 3) * 2;
            float b0 = bias[col], b1 = bias[col + 1];
            *(uint32_t*)(C + (size_t)row0 * N + col) =
                pack_h2(acc[ma][na][0] + b0, acc[ma][na][1] + b1);
            *(uint32_t*)(C + (size_t)(row0 + 8) * N + col) =
                pack_h2(acc[ma][na][2] + b0, acc[ma][na][3] + b1);
        }
    }
}

__device__ __forceinline__ float sigmoidf_(float v) { return 1.f / (1.f + expf(-v)); }

// ========================= scan common =======================================
#define W_STR 520
#define A_STR 264
#define W_SPL_BYTES (32 * W_STR * 2)
#define SCAN_W_BYTES (2 * W_SPL_BYTES)                    // 66560
#define SCAN1_SMEM (SCAN_W_BYTES + 2 * 64 * A_STR * 2)    // 134144
// scan0 batch-split: W hi-only 64 rows + 2 x 64-row A buffers
#define S0_W_BYTES (64 * W_STR * 2)                       // 66560
#define S0_ABUF (64 * A_STR * 2)                          // 33792
#define SCAN0_SMEM (S0_W_BYTES + 2 * S0_ABUF)             // 134144

template<int MC>
__device__ __forceinline__ void stage_chunk(uint32_t dst, const __half* hs,
                                            int bbase, int kb, int tid) {
#pragma unroll
    for (int i = 0; i < MC / 8; i++) {
        int e = tid + i * 256;
        int row = e >> 5, seg = e & 31;
        const __half* src = hs + (size_t)(bbase + row) * HH + kb + seg * 8;
        CP_ASYNC16(dst + (row * A_STR + seg * 8) * 2, src);
    }
}

// hi+lo chunk (layer-1, proven R12)
__device__ __forceinline__ void mma_chunk(uint32_t AB, uint32_t WHI, uint32_t WLO,
                                          int mrow, int kg0,
                                          uint32_t a_row, uint32_t a_col,
                                          uint32_t b_n, uint32_t b_k,
                                          float acc[4][4]) {
#pragma unroll
    for (int kk = 0; kk < 16; kk++) {
        uint32_t a[4];
        ldsm4(a, AB + ((mrow + a_row) * A_STR + kk * 16 + a_col) * 2);
        int kg = kg0 + kk * 16;
        uint32_t bh0[4], bh1[4], bl0[4], bl1[4];
        ldsm4(bh0, WHI + (b_n * W_STR + kg + b_k) * 2);
        ldsm4(bh1, WHI + ((16 + b_n) * W_STR + kg + b_k) * 2);
        ldsm4(bl0, WLO + (b_n * W_STR + kg + b_k) * 2);
        ldsm4(bl1, WLO + ((16 + b_n) * W_STR + kg + b_k) * 2);
        mma_f16(acc[0], a, bh0[0], bh0[1]);
        mma_f16(acc[0], a, bl0[0], bl0[1]);
        mma_f16(acc[1], a, bh0[2], bh0[3]);
        mma_f16(acc[1], a, bl0[2], bl0[3]);
        mma_f16(acc[2], a, bh1[0], bh1[1]);
        mma_f16(acc[2], a, bl1[0], bl1[1]);
        mma_f16(acc[3], a, bh1[2], bh1[3]);
        mma_f16(acc[3], a, bl1[2], bl1[3]);
    }
}

// hi-only chunk (layer-0 batch-split)
__device__ __forceinline__ void mma_chunk_hi(uint32_t AB, uint32_t WHIb,
                                             int mrow, int kg0,
                                             uint32_t a_row, uint32_t a_col,
                                             uint32_t b_n, uint32_t b_k,
                                             float acc[4][4]) {
#pragma unroll
    for (int kk = 0; kk < 16; kk++) {
        uint32_t a[4];
        ldsm4(a, AB + ((mrow + a_row) * A_STR + kk * 16 + a_col) * 2);
        int kg = kg0 + kk * 16;
        uint32_t bh0[4], bh1[4];
        ldsm4(bh0, WHIb + (b_n * W_STR + kg + b_k) * 2);
        ldsm4(bh1, WHIb + ((16 + b_n) * W_STR + kg + b_k) * 2);
        mma_f16(acc[0], a, bh0[0], bh0[1]);
        mma_f16(acc[1], a, bh0[2], bh0[3]);
        mma_f16(acc[2], a, bh1[0], bh1[1]);
        mma_f16(acc[3], a, bh1[2], bh1[3]);
    }
}

// ========================= layer-0 scan: batch-split, W hi-only ==============
// 128 CTAs = 2 dir x 32 slices(16 units) x 2 batch-halves.
// 8 warps = 4 m-tiles(16 batches) x 2 unit-groups(8 units, 32 W rows each).
__global__ __launch_bounds__(256, 1) void scan0_bs(
    const __half* __restrict__ xgf, const __half* __restrict__ xgr,
    const float* __restrict__ whhf, const float* __restrict__ whhr,
    const float* __restrict__ bhhf, const float* __restrict__ bhhr,
    __half* __restrict__ hrec, __half* __restrict__ houth,
    int* __restrict__ bar) {
    extern __shared__ __align__(16) char smem[];
    const uint32_t sb  = smem_to_u32(smem);
    const uint32_t WHI = sb;
    const uint32_t AB0 = sb + S0_W_BYTES, AB1 = AB0 + S0_ABUF;

    const int tid = threadIdx.x, lane = tid & 31, wid = tid >> 5;
    const int dir   = blockIdx.x >> 6;
    const int rest  = blockIdx.x & 63;
    const int slice = rest >> 1;        // 0..31 (16 units each)
    const int bg    = rest & 1;
    const int j0    = slice * 16;
    const int bbase = bg * 64;
    const int bsub  = rest & 7;

    const float* whh = dir ? whhr : whhf;
    const float* bhh = dir ? bhhr : bhhf;
    const __half* xg = dir ? xgr  : xgf;
    int* barp = bar + dir * BAR_GRP;
    __half* hbuf = hrec + (size_t)dir * 2 * BB * HH;

    // W: 64 rows, n = wn*32 + g*8 + u  <-  whh[g*512 + j0 + wn*8 + u], hi only
#pragma unroll
    for (int i = 0; i < 32; i++) {
        int idx = tid + i * 256;               // 0..8191 float4
        int n = idx >> 7, c4 = idx & 127;
        int wn_ = n >> 5, m5 = n & 31;
        int grow = (m5 >> 3) * 512 + j0 + wn_ * 8 + (m5 & 7);
        float4 v = *(const float4*)(whh + (size_t)grow * 512 + c4 * 4);
        wh_store(WHI + (n * W_STR + c4 * 4) * 2, v);
    }
    __syncthreads();

    const uint32_t a_row = lane & 15;
    const uint32_t a_col = (lane >> 4) << 3;
    const uint32_t b_n   = (lane & 7) + ((lane >> 4) << 3);
    const uint32_t b_k   = ((lane >> 3) & 1) << 3;
    const int r = lane >> 2;
    const int u = (lane & 3) * 2;
    const int wm = wid & 3;
    const int wn = wid >> 2;
    const int mrow = wm * 16;
    const uint32_t WHIb = WHI + wn * 32 * W_STR * 2;
    const int ju = j0 + wn * 8 + u;            // absolute unit index (pair base)
    const int b0 = bbase + mrow + r;

    float bias[4][2];
#pragma unroll
    for (int g = 0; g < 4; g++) {
        bias[g][0] = bhh[g * 512 + ju];
        bias[g][1] = bhh[g * 512 + ju + 1];
    }
    float c[4] = {0.f, 0.f, 0.f, 0.f};

    uint32_t xrn[4][2];
    {
        const int t0 = dir ? (TT - 1) : 0;
        const __half* xp = xg + ((size_t)t0 * BB + b0) * G4H + ju;
#pragma unroll
        for (int g = 0; g < 4; g++)
#pragma unroll
            for (int rp = 0; rp < 2; rp++)
                xrn[g][rp] = *(const uint32_t*)(xp + (size_t)rp * 8 * G4H + g * 512);
    }

    for (int step = 0; step < TT; step++) {
        const int t = dir ? (TT - 1 - step) : step;

        uint32_t xr[4][2];
#pragma unroll
        for (int g = 0; g < 4; g++)
#pragma unroll
            for (int rp = 0; rp < 2; rp++) xr[g][rp] = xrn[g][rp];

        float acc[4][4];
#pragma unroll
        for (int g = 0; g < 4; g++)
#pragma unroll
            for (int k = 0; k < 4; k++) acc[g][k] = 0.f;

        if (step > 0) {
            const int rpar = (step - 1) & 1;
            const __half* hs = hbuf + (size_t)rpar * BB * HH;
            stage_chunk<64>(AB0, hs, bbase, 0, tid);   CP_COMMIT;
            stage_chunk<64>(AB1, hs, bbase, 256, tid); CP_COMMIT;
            CP_WAIT_1;
            __syncthreads();
            mma_chunk_hi(AB0, WHIb, mrow, 0, a_row, a_col, b_n, b_k, acc);
            CP_WAIT_0;
            __syncthreads();
            mma_chunk_hi(AB1, WHIb, mrow, 256, a_row, a_col, b_n, b_k, acc);
        }

        {
            const int wpar = step & 1;
            __half* dh = hbuf + (size_t)wpar * BB * HH;
#pragma unroll
            for (int rp = 0; rp < 2; rp++) {
                const int b = b0 + rp * 8;
                float hv2[2];
#pragma unroll
                for (int cc = 0; cc < 2; cc++) {
                    const int k = rp * 2 + cc;
                    float2 x0 = __half22float2(*(__half2*)&xr[0][rp]);
                    float2 x1 = __half22float2(*(__half2*)&xr[1][rp]);
                    float2 x2 = __half22float2(*(__half2*)&xr[2][rp]);
                    float2 x3 = __half22float2(*(__half2*)&xr[3][rp]);
                    float gi = acc[0][k] + (cc ? x0.y : x0.x) + bias[0][cc];
                    float gf = acc[1][k] + (cc ? x1.y : x1.x) + bias[1][cc];
                    float gg = acc[2][k] + (cc ? x2.y : x2.x) + bias[2][cc];
                    float go = acc[3][k] + (cc ? x3.y : x3.x) + bias[3][cc];
                    float cv = sigmoidf_(gf) * c[k] + sigmoidf_(gi) * tanhf(gg);
                    c[k] = cv;
                    hv2[cc] = sigmoidf_(go) * tanhf(cv);
                }
                uint32_t p = pack_h2(hv2[0], hv2[1]);
                *(uint32_t*)(dh + (size_t)b * HH + ju) = p;
                *(uint32_t*)(houth + ((size_t)t * BB + b) * 1024 + dir * 512 + ju) = p;
            }
        }

        if (step < TT - 1) {
            // prefetch next xg before the barrier
            {
                const int tn = dir ? (TT - 2 - step) : (step + 1);
                const __half* xp = xg + ((size_t)tn * BB + b0) * G4H + ju;
#pragma unroll
                for (int g = 0; g < 4; g++)
#pragma unroll
                    for (int rp = 0; rp < 2; rp++)
                        xrn[g][rp] = *(const uint32_t*)(xp + (size_t)rp * 8 * G4H + g * 512);
            }
            __threadfence();
            __syncthreads();
            if (tid == 0)
                bar_arrive_wait(barp + step * BAR_STEP, bsub, 64);
            __syncthreads();
        }
    }
}

// ========================= layer-1 scan (R12 proven) =========================
__global__ __launch_bounds__(256, 1) void scan1_mma(
    const __half* __restrict__ xg,
    const float* __restrict__ whh, const float* __restrict__ bhh,
    __half* __restrict__ hrec, float* __restrict__ houtf,
    int* __restrict__ bar) {
    constexpr int MC = 64;
    constexpr int ASZ = MC * A_STR * 2;
    extern __shared__ __align__(16) char smem[];
    const uint32_t sb  = smem_to_u32(smem);
    const uint32_t WHI = sb, WLO = sb + W_SPL_BYTES;
    const uint32_t AB0 = sb + SCAN_W_BYTES, AB1 = AB0 + ASZ;

    const int tid = threadIdx.x, lane = tid & 31, wid = tid >> 5;
    const int grp   = blockIdx.x >> 6;
    const int slice = blockIdx.x & 63;
    const int j0    = slice * 8;
    const int bbase = grp * 64;
    const int bsub  = slice & 7;

    int* barp = bar + grp * BAR_GRP;
    __half* hbuf = hrec;

#pragma unroll
    for (int i = 0; i < 16; i++) {
        int idx = tid + i * 256;
        int n = idx >> 7, c4 = idx & 127;
        int grow = (n >> 3) * 512 + j0 + (n & 7);
        float4 v = *(const float4*)(whh + (size_t)grow * 512 + c4 * 4);
        uint32_t off = (n * W_STR + c4 * 4) * 2;
        splitw_store(WHI + off, WLO + off, v);
    }
    __syncthreads();

    const uint32_t a_row = lane & 15;
    const uint32_t a_col = (lane >> 4) << 3;
    const uint32_t b_n   = (lane & 7) + ((lane >> 4) << 3);
    const uint32_t b_k   = ((lane >> 3) & 1) << 3;
    const int r = lane >> 2;
    const int u = (lane & 3) * 2;
    const int wm = wid & 3;
    const int mrow = wm * 16;
    const bool owner = (wid < 4);

    float bias[4][2];
#pragma unroll
    for (int g = 0; g < 4; g++) {
        bias[g][0] = bhh[g * 512 + j0 + u];
        bias[g][1] = bhh[g * 512 + j0 + u + 1];
    }
    float c[4] = {0.f, 0.f, 0.f, 0.f};

    uint32_t xrn[4][2];
    if (owner) {
        const __half* xp = xg + ((size_t)(bbase + mrow + r)) * G4H + j0 + u;
#pragma unroll
        for (int g = 0; g < 4; g++)
#pragma unroll
            for (int rp = 0; rp < 2; rp++)
                xrn[g][rp] = *(const uint32_t*)(xp + (size_t)rp * 8 * G4H + g * 512);
    }

    for (int step = 0; step < TT; step++) {
        const int t = step;

        uint32_t xr[4][2];
#pragma unroll
        for (int g = 0; g < 4; g++)
#pragma unroll
            for (int rp = 0; rp < 2; rp++) xr[g][rp] = xrn[g][rp];

        float acc[4][4];
#pragma unroll
        for (int g = 0; g < 4; g++)
#pragma unroll
            for (int k = 0; k < 4; k++) acc[g][k] = 0.f;

        if (step > 0) {
            const int rpar = (step - 1) & 1;
            const __half* hs = hbuf + (size_t)rpar * BB * HH;
            stage_chunk<MC>(AB0, hs, bbase, 0, tid);   CP_COMMIT;
            stage_chunk<MC>(AB1, hs, bbase, 256, tid); CP_COMMIT;
            CP_WAIT_0;
            __syncthreads();
            const int ks = wid >> 2;
            mma_chunk(ks ? AB1 : AB0, WHI, WLO, mrow, ks * 256,
                      a_row, a_col, b_n, b_k, acc);
        }

        __syncthreads();
        if (wid >= 4) {
            uint32_t base = AB0 + ((wid - 4) * 32 + lane) * 4;
#pragma unroll
            for (int f = 0; f < 16; f++)
                *(float*)(smem + (base - sb) + f * 512) = acc[f >> 2][f & 3];
        }
        __syncthreads();
        if (wid < 4) {
            uint32_t base = AB0 + (wid * 32 + lane) * 4;
#pragma unroll
            for (int f = 0; f < 16; f++)
                acc[f >> 2][f & 3] += *(float*)(smem + (base - sb) + f * 512);
        }

        if (owner) {
            const int wpar = step & 1;
            __half* dh = hbuf + (size_t)wpar * BB * HH;
#pragma unroll
            for (int rp = 0; rp < 2; rp++) {
                const int b = bbase + mrow + r + rp * 8;
                float hv2[2];
#pragma unroll
                for (int cc = 0; cc < 2; cc++) {
                    const int k = rp * 2 + cc;
                    float2 x0 = __half22float2(*(__half2*)&xr[0][rp]);
                    float2 x1 = __half22float2(*(__half2*)&xr[1][rp]);
                    float2 x2 = __half22float2(*(__half2*)&xr[2][rp]);
                    float2 x3 = __half22float2(*(__half2*)&xr[3][rp]);
                    float gi = acc[0][k] + (cc ? x0.y : x0.x) + bias[0][cc];
                    float gf = acc[1][k] + (cc ? x1.y : x1.x) + bias[1][cc];
                    float gg = acc[2][k] + (cc ? x2.y : x2.x) + bias[2][cc];
                    float go = acc[3][k] + (cc ? x3.y : x3.x) + bias[3][cc];
                    float cv = sigmoidf_(gf) * c[k] + sigmoidf_(gi) * tanhf(gg);
                    c[k] = cv;
                    hv2[cc] = sigmoidf_(go) * tanhf(cv);
                }
                if (t == TT - 1) {
                    *(float2*)(houtf + (size_t)b * HH + j0 + u) =
                        make_float2(hv2[0], hv2[1]);
                }
                *(uint32_t*)(dh + (size_t)b * HH + j0 + u) = pack_h2(hv2[0], hv2[1]);
            }
        }

        if (step < TT - 1) {
            if (owner) {
                const __half* xp = xg + ((size_t)((step + 1) * BB + bbase + mrow + r)) * G4H + j0 + u;
#pragma unroll
                for (int g = 0; g < 4; g++)
#pragma unroll
                    for (int rp = 0; rp < 2; rp++)
                        xrn[g][rp] = *(const uint32_t*)(xp + (size_t)rp * 8 * G4H + g * 512);
            }
            __threadfence();
            __syncthreads();
            if (tid == 0)
                bar_arrive_wait(barp + step * BAR_STEP, bsub, 64);
            __syncthreads();
        }
    }
}

// ========================= layer-1 reverse at t = T-1 ========================
__global__ void hr_last_kernel(const __half* __restrict__ xg,
                               const float* __restrict__ bhh,
                               float* __restrict__ hr) {
    int idx = blockIdx.x * blockDim.x + threadIdx.x;
    if (idx >= BB * HH) return;
    int b = idx >> 9, j = idx & 511;
    float gi = __half2float(xg[(size_t)b * G4H + j])        + bhh[j];
    float gg = __half2float(xg[(size_t)b * G4H + 1024 + j]) + bhh[1024 + j];
    float go = __half2float(xg[(size_t)b * G4H + 1536 + j]) + bhh[1536 + j];
    float cv = sigmoidf_(gi) * tanhf(gg);
    hr[idx] = sigmoidf_(go) * tanhf(cv);
}

// ========================= final projection ==================================
__global__ void out_kernel(const float* __restrict__ hf, const float* __restrict__ hr,
                           const float* __restrict__ wout, const float* __restrict__ bout,
                           float* __restrict__ out) {
    int b = blockIdx.x;
    int warp = threadIdx.x >> 5;
    int lane = threadIdx.x & 31;
    float s = 0.f;
    for (int k = lane; k < 512; k += 32) s += hf[(size_t)b * HH + k] * wout[warp * 1024 + k];
    for (int k = lane; k < 512; k += 32) s += hr[(size_t)b * HH + k] * wout[warp * 1024 + 512 + k];
#pragma unroll
    for (int off = 16; off; off >>= 1) s += __shfl_xor_sync(0xffffffffu, s, off);
    if (lane == 0) out[b * NCLS + warp] = s + bout[warp];
}

// ========================= host launch =======================================
extern "C" void kernel_launch(void* const* d_in, const int* in_sizes, int n_in,
                              void* d_out, int out_size) {
    const int*   x     = (const int*)  d_in[0];
    const float* emb   = (const float*)d_in[1];
    const float* wih0f = (const float*)d_in[2];
    const float* whh0f = (const float*)d_in[3];
    const float* bih0f = (const float*)d_in[4];
    const float* bhh0f = (const float*)d_in[5];
    const float* wih0r = (const float*)d_in[6];
    const float* whh0r = (const float*)d_in[7];
    const float* bih0r = (const float*)d_in[8];
    const float* bhh0r = (const float*)d_in[9];
    const float* wih1f = (const float*)d_in[10];
    const float* whh1f = (const float*)d_in[11];
    const float* bih1f = (const float*)d_in[12];
    const float* bhh1f = (const float*)d_in[13];
    const float* wih1r = (const float*)d_in[14];
    const float* whh1r = (const float*)d_in[15]; (void)whh1r;
    const float* bih1r = (const float*)d_in[16];
    const float* bhh1r = (const float*)d_in[17];
    const float* wout  = (const float*)d_in[18];
    const float* bout  = (const float*)d_in[19];
    float* out = (float*)d_out;

    __half *p_x0, *p_h0, *p_hf0, *p_hf1, *p_xg0f, *p_xg0r, *p_xg1f, *p_xg1r;
    float *p_h1f, *p_hr1;
    int *p_bar0, *p_bar1;
    cudaGetSymbolAddress((void**)&p_x0,   g_x0);
    cudaGetSymbolAddress((void**)&p_xg0f, g_xg0f);
    cudaGetSymbolAddress((void**)&p_xg0r, g_xg0r);
    cudaGetSymbolAddress((void**)&p_h0,   g_h0);
    cudaGetSymbolAddress((void**)&p_xg1f, g_xg1f);
    cudaGetSymbolAddress((void**)&p_xg1r, g_xg1r);
    cudaGetSymbolAddress((void**)&p_hf0,  g_hf0);
    cudaGetSymbolAddress((void**)&p_hf1,  g_hf1);
    cudaGetSymbolAddress((void**)&p_h1f,  g_h1f);
    cudaGetSymbolAddress((void**)&p_hr1,  g_hr1);
    cudaGetSymbolAddress((void**)&p_bar0, g_bar0);
    cudaGetSymbolAddress((void**)&p_bar1, g_bar1);

    cudaFuncSetAttribute(scan0_bs,  cudaFuncAttributeMaxDynamicSharedMemorySize, SCAN0_SMEM);
    cudaFuncSetAttribute(scan1_mma, cudaFuncAttributeMaxDynamicSharedMemorySize, SCAN1_SMEM);

    reset_kernel<<<128, 256>>>();
    embed_kernel<<<(TT * BB * (DEMB / 4) + 255) / 256, 256>>>(x, emb, p_x0);

    dim3 gBig(G4H / 128, (TT * BB) / 128);   // (16, 256)
    gemm_mma<<<gBig, 256>>>(p_x0, wih0f, bih0f, p_xg0f, TT * BB, G4H, DEMB);
    gemm_mma<<<gBig, 256>>>(p_x0, wih0r, bih0r, p_xg0r, TT * BB, G4H, DEMB);

    scan0_bs<<<128, 256, SCAN0_SMEM>>>(p_xg0f, p_xg0r, whh0f, whh0r,
                                       bhh0f, bhh0r, p_hf0, p_h0, p_bar0);

    gemm_mma<<<gBig, 256>>>(p_h0, wih1f, bih1f, p_xg1f, TT * BB, G4H, 2 * HH);
    gemm_mma<<<dim3(G4H / 128, 1), 256>>>(
        p_h0 + (size_t)(TT - 1) * BB * 1024, wih1r, bih1r, p_xg1r, BB, G4H, 2 * HH);

    scan1_mma<<<128, 256, SCAN1_SMEM>>>(p_xg1f, whh1f, bhh1f, p_hf1, p_h1f, p_bar1);

    hr_last_kernel<<<(BB * HH) / 256, 256>>>(p_xg1r, bhh1r, p_hr1);

    out_kernel<<<BB, 160>>>(p_h1f, p_hr1, wout, bout, out);
}

// round 16
// speedup vs baseline: 1.2119x; 1.0132x over previous
#include <cuda_runtime.h>
#include <cuda_fp16.h>
#include <math.h>
#include <cstdint>

#define TT 256
#define BB 128
#define HH 512
#define DEMB 256
#define PAD_IDX 29999
#define NCLS 5
#define G4H 2048  // 4*HH

#define BAR_SUB 8
#define BAR_SPC 32
#define BAR_STEP (BAR_SUB * BAR_SPC)
#define BAR_GRP  (TT * BAR_STEP)

__device__ __forceinline__ uint32_t smem_to_u32(const void* p) {
    uint32_t a;
    asm("{ .reg .u64 t; cvta.to.shared.u64 t, %1; cvt.u32.u64 %0, t; }" : "=r"(a) : "l"(p));
    return a;
}
#define CP_ASYNC16(dst, src) \
    asm volatile("cp.async.cg.shared.global [%0], [%1], 16;" :: "r"(dst), "l"(src))
#define CP_COMMIT  asm volatile("cp.async.commit_group;" ::: "memory")
#define CP_WAIT_1  asm volatile("cp.async.wait_group 1;" ::: "memory")
#define CP_WAIT_0  asm volatile("cp.async.wait_group 0;" ::: "memory")

// ========================= scratch (static, no allocs) =======================
__device__ __half g_x0 [(size_t)TT * BB * DEMB];
__device__ __half g_xg0f[(size_t)TT * BB * G4H];
__device__ __half g_xg0r[(size_t)TT * BB * G4H];
__device__ __half g_h0 [(size_t)TT * BB * 2 * HH];
__device__ __half g_xg1f[(size_t)TT * BB * G4H];
__device__ __half g_xg1r[(size_t)BB * G4H];
__device__ __half g_hf0[2 * 2 * BB * HH];
__device__ __half g_hf1[2 * BB * HH];
__device__ float g_h1f [BB * HH];
__device__ float g_hr1 [BB * HH];
__device__ int g_bar0[2 * BAR_GRP];
__device__ int g_bar1[BAR_GRP];

__global__ void reset_kernel() {
    int n0 = 2 * BAR_GRP;
    for (int i = blockIdx.x * blockDim.x + threadIdx.x; i < n0;
         i += gridDim.x * blockDim.x) {
        g_bar0[i] = 0;
        if (i < BAR_GRP) g_bar1[i] = 0;
    }
}

__device__ __forceinline__ uint32_t pack_h2(float a, float b) {
    __half2 h = __floats2half2_rn(a, b);
    return *(uint32_t*)&h;
}

__device__ __forceinline__ void bar_arrive_wait(int* base, int sub, int target) {
    atomicAdd(base + sub * BAR_SPC, 1);
    for (;;) {
        int sum = 0;
#pragma unroll
        for (int s = 0; s < BAR_SUB; s++) {
            int v;
            asm volatile("ld.global.cg.b32 %0, [%1];" : "=r"(v)
                         : "l"(base + s * BAR_SPC));
            sum += v;
        }
        if (sum >= target) break;
        __nanosleep(32);
    }
}

// ========================= embedding gather (fp16 out) =======================
__global__ void embed_kernel(const int* __restrict__ x,
                             const float* __restrict__ emb,
                             __half* __restrict__ out) {
    int gid = blockIdx.x * blockDim.x + threadIdx.x;
    if (gid >= TT * BB * (DEMB / 4)) return;
    int i4  = gid & 63;
    int row = gid >> 6;
    int t = row / BB;
    int b = row - t * BB;
    int xi = x[b * TT + t];
    float4 v;
    if (xi == PAD_IDX) { v.x = v.y = v.z = v.w = 0.f; }
    else               { v = ((const float4*)emb)[(size_t)xi * 64 + i4]; }
    uint2 p;
    p.x = pack_h2(v.x, v.y);
    p.y = pack_h2(v.z, v.w);
    ((uint2*)out)[gid] = p;
}

// ========================= mma primitives ====================================
__device__ __forceinline__ void ldsm4(uint32_t* r, uint32_t addr) {
    asm volatile("ldmatrix.sync.aligned.m8n8.x4.shared.b16 {%0,%1,%2,%3}, [%4];"
        : "=r"(r[0]), "=r"(r[1]), "=r"(r[2]), "=r"(r[3]) : "r"(addr));
}
__device__ __forceinline__ void mma_f16(float* d, const uint32_t* a,
                                        uint32_t b0, uint32_t b1) {
    asm volatile("mma.sync.aligned.m16n8k16.row.col.f32.f16.f16.f32 "
        "{%0,%1,%2,%3}, {%4,%5,%6,%7}, {%8,%9}, {%0,%1,%2,%3};"
        : "+f"(d[0]), "+f"(d[1]), "+f"(d[2]), "+f"(d[3])
        : "r"(a[0]), "r"(a[1]), "r"(a[2]), "r"(a[3]), "r"(b0), "r"(b1));
}
__device__ __forceinline__ void splitw_store(uint32_t hiA, uint32_t loA, float4 v) {
    __half h0 = __float2half_rn(v.x), h1 = __float2half_rn(v.y);
    __half h2 = __float2half_rn(v.z), h3 = __float2half_rn(v.w);
    float r0 = v.x - __half2float(h0), r1 = v.y - __half2float(h1);
    float r2 = v.z - __half2float(h2), r3 = v.w - __half2float(h3);
    uint32_t hp0 = pack_h2(__half2float(h0), __half2float(h1));
    uint32_t hp1 = pack_h2(__half2float(h2), __half2float(h3));
    uint32_t lp0 = pack_h2(r0, r1);
    uint32_t lp1 = pack_h2(r2, r3);
    asm volatile("st.shared.v2.b32 [%0], {%1, %2};" :: "r"(hiA), "r"(hp0), "r"(hp1) : "memory");
    asm volatile("st.shared.v2.b32 [%0], {%1, %2};" :: "r"(loA), "r"(lp0), "r"(lp1) : "memory");
}
__device__ __forceinline__ void wh_store(uint32_t hiA, float4 v) {
    uint32_t hp0 = pack_h2(v.x, v.y);
    uint32_t hp1 = pack_h2(v.z, v.w);
    asm volatile("st.shared.v2.b32 [%0], {%1, %2};" :: "r"(hiA), "r"(hp0), "r"(hp1) : "memory");
}

// ========================= fp16-A GEMM: C(fp16) = A*W^T + bias ===============
#define KC  32
#define LDH 40
#define GA_BYTES (128 * LDH * 2)

__global__ __launch_bounds__(256, 2) void gemm_mma(const __half* __restrict__ A,
                                                   const float* __restrict__ W,
                                                   const float* __restrict__ bias,
                                                   __half* __restrict__ C,
                                                   int M, int N, int K) {
    __shared__ __align__(16) __half gsm[4 * 128 * LDH];
    const uint32_t sb  = smem_to_u32(gsm);
    const uint32_t AH0 = sb, AH1 = sb + GA_BYTES;
    const uint32_t BH  = sb + 2 * GA_BYTES, BL = BH + GA_BYTES;

    const int tid  = threadIdx.x;
    const int lane = tid & 31;
    const int wid  = tid >> 5;
    const int wm   = wid & 3;
    const int wn   = wid >> 2;
    const int bm   = blockIdx.y * 128;
    const int bn   = blockIdx.x * 128;

    float acc[2][8][4];
#pragma unroll
    for (int i = 0; i < 2; i++)
#pragma unroll
        for (int j = 0; j < 8; j++)
#pragma unroll
            for (int k = 0; k < 4; k++) acc[i][j][k] = 0.f;

    const uint32_t a_row = lane & 15;
    const uint32_t a_col = (lane >> 4) << 3;
    const uint32_t b_n   = (lane & 7) + ((lane >> 4) << 3);
    const uint32_t b_k   = ((lane >> 3) & 1) << 3;

    const int s_row = tid >> 2, s_c8 = tid & 3;
    const int w_row = tid >> 3, w_c4 = tid & 7;

    float4 vw[4];
#pragma unroll
    for (int i = 0; i < 2; i++) {
        int row = s_row + i * 64;
        CP_ASYNC16(AH0 + (row * LDH + s_c8 * 8) * 2,
                   A + (size_t)(bm + row) * K + s_c8 * 8);
    }
    CP_COMMIT;
#pragma unroll
    for (int i = 0; i < 4; i++) {
        int row = w_row + i * 32;
        vw[i] = *(const float4*)(W + (size_t)(bn + row) * K + w_c4 * 4);
    }

    const int nch = K / KC;
    for (int ch = 0; ch < nch; ch++) {
        const int kb = ch * KC;
        if (ch + 1 < nch) {
            uint32_t dst = ((ch + 1) & 1) ? AH1 : AH0;
#pragma unroll
            for (int i = 0; i < 2; i++) {
                int row = s_row + i * 64;
                CP_ASYNC16(dst + (row * LDH + s_c8 * 8) * 2,
                           A + (size_t)(bm + row) * K + kb + KC + s_c8 * 8);
            }
            CP_COMMIT;
        }
#pragma unroll
        for (int i = 0; i < 4; i++) {
            int row = w_row + i * 32;
            uint32_t off = (row * LDH + w_c4 * 4) * 2;
            splitw_store(BH + off, BL + off, vw[i]);
        }
        if (ch + 1 < nch) {
#pragma unroll
            for (int i = 0; i < 4; i++) {
                int row = w_row + i * 32;
                vw[i] = *(const float4*)(W + (size_t)(bn + row) * K + kb + KC + w_c4 * 4);
            }
        }
        if (ch + 1 < nch) { CP_WAIT_1; } else { CP_WAIT_0; }
        __syncthreads();

        const uint32_t AH = (ch & 1) ? AH1 : AH0;
#pragma unroll
        for (int ks = 0; ks < KC; ks += 16) {
            uint32_t ah[2][4];
#pragma unroll
            for (int ma = 0; ma < 2; ma++)
                ldsm4(ah[ma], AH + ((wm * 32 + ma * 16 + a_row) * LDH + ks + a_col) * 2);
#pragma unroll
            for (int bg = 0; bg < 4; bg++) {
                uint32_t boff = ((wn * 64 + bg * 16 + b_n) * LDH + ks + b_k) * 2;
                uint32_t bh[4], bl[4];
                ldsm4(bh, BH + boff);
                ldsm4(bl, BL + boff);
#pragma unroll
                for (int ma = 0; ma < 2; ma++) {
#pragma unroll
                    for (int na = 0; na < 2; na++) {
                        float* d = acc[ma][bg * 2 + na];
                        mma_f16(d, ah[ma], bh[na * 2], bh[na * 2 + 1]);
                        mma_f16(d, ah[ma], bl[na * 2], bl[na * 2 + 1]);
                    }
                }
            }
        }
        __syncthreads();
    }

#pragma unroll
    for (int ma = 0; ma < 2; ma++) {
        int row0 = bm + wm * 32 + ma * 16 + (lane >> 2);
#pragma unroll
        for (int na = 0; na < 8; na++) {
            int col = bn + wn * 64 + na * 8 + (lane & 3) * 2;
            float b0 = bias[col], b1 = bias[col + 1];
            *(uint32_t*)(C + (size_t)row0 * N + col) =
                pack_h2(acc[ma][na][0] + b0, acc[ma][na][1] + b1);
            *(uint32_t*)(C + (size_t)(row0 + 8) * N + col) =
                pack_h2(acc[ma][na][2] + b0, acc[ma][na][3] + b1);
        }
    }
}

__device__ __forceinline__ float sigmoidf_(float v) { return 1.f / (1.f + expf(-v)); }

// ========================= scan (batch-split, W hi-only, unified) ============
// L0: 128 CTAs = 2 dir x (32 slices x 2 batch-halves); L1: 64 CTAs = 32 x 2.
// CTA: M=64 batches, N=64 gate-rows (16 units), K=512.
// 8 warps = 4 m-tiles(16 batches) x 2 unit-groups(8 units = 32 W rows).
#define W_STR 520
#define A_STR 264
#define S0_W_BYTES (64 * W_STR * 2)                       // 66560
#define S0_ABUF (64 * A_STR * 2)                          // 33792
#define SCAN_SMEM (S0_W_BYTES + 2 * S0_ABUF)              // 134144

__device__ __forceinline__ void stage64(uint32_t dst, const __half* hs,
                                        int bbase, int kb, int tid) {
#pragma unroll
    for (int i = 0; i < 8; i++) {
        int e = tid + i * 256;
        int row = e >> 5, seg = e & 31;
        const __half* src = hs + (size_t)(bbase + row) * HH + kb + seg * 8;
        CP_ASYNC16(dst + (row * A_STR + seg * 8) * 2, src);
    }
}

__device__ __forceinline__ void mma_chunk_hi(uint32_t AB, uint32_t WHIb,
                                             int mrow, int kg0,
                                             uint32_t a_row, uint32_t a_col,
                                             uint32_t b_n, uint32_t b_k,
                                             float acc[4][4]) {
#pragma unroll
    for (int kk = 0; kk < 16; kk++) {
        uint32_t a[4];
        ldsm4(a, AB + ((mrow + a_row) * A_STR + kk * 16 + a_col) * 2);
        int kg = kg0 + kk * 16;
        uint32_t bh0[4], bh1[4];
        ldsm4(bh0, WHIb + (b_n * W_STR + kg + b_k) * 2);
        ldsm4(bh1, WHIb + ((16 + b_n) * W_STR + kg + b_k) * 2);
        mma_f16(acc[0], a, bh0[0], bh0[1]);
        mma_f16(acc[1], a, bh0[2], bh0[3]);
        mma_f16(acc[2], a, bh1[0], bh1[1]);
        mma_f16(acc[3], a, bh1[2], bh1[3]);
    }
}

template<bool L0>
__global__ __launch_bounds__(256, 1) void scan_bs(
    const __half* __restrict__ xgf, const __half* __restrict__ xgr,
    const float* __restrict__ whhf, const float* __restrict__ whhr,
    const float* __restrict__ bhhf, const float* __restrict__ bhhr,
    __half* __restrict__ hrec, __half* __restrict__ houth,
    float* __restrict__ houtf, int* __restrict__ bar) {
    extern __shared__ __align__(16) char smem[];
    const uint32_t sb  = smem_to_u32(smem);
    const uint32_t WHI = sb;
    const uint32_t AB0 = sb + S0_W_BYTES, AB1 = AB0 + S0_ABUF;

    const int tid = threadIdx.x, lane = tid & 31, wid = tid >> 5;
    const int dir   = L0 ? (int)(blockIdx.x >> 6) : 0;
    const int rest  = L0 ? (int)(blockIdx.x & 63) : (int)blockIdx.x;
    const int slice = rest >> 1;
    const int bg    = rest & 1;
    const int j0    = slice * 16;
    const int bbase = bg * 64;
    const int bsub  = rest & 7;

    const float* whh = (L0 && dir) ? whhr : whhf;
    const float* bhh = (L0 && dir) ? bhhr : bhhf;
    const __half* xg = (L0 && dir) ? xgr  : xgf;
    int* barp = bar + (L0 ? dir * BAR_GRP : 0);
    __half* hbuf = hrec + (L0 ? (size_t)dir * 2 * BB * HH : 0);

    // W: 64 rows, n = wn*32 + g*8 + u  <-  whh[g*512 + j0 + wn*8 + u], hi only
#pragma unroll
    for (int i = 0; i < 32; i++) {
        int idx = tid + i * 256;
        int n = idx >> 7, c4 = idx & 127;
        int wn_ = n >> 5, m5 = n & 31;
        int grow = (m5 >> 3) * 512 + j0 + wn_ * 8 + (m5 & 7);
        float4 v = *(const float4*)(whh + (size_t)grow * 512 + c4 * 4);
        wh_store(WHI + (n * W_STR + c4 * 4) * 2, v);
    }
    __syncthreads();

    const uint32_t a_row = lane & 15;
    const uint32_t a_col = (lane >> 4) << 3;
    const uint32_t b_n   = (lane & 7) + ((lane >> 4) << 3);
    const uint32_t b_k   = ((lane >> 3) & 1) << 3;
    const int r = lane >> 2;
    const int u = (lane & 3) * 2;
    const int wm = wid & 3;
    const int wn = wid >> 2;
    const int mrow = wm * 16;
    const uint32_t WHIb = WHI + wn * 32 * W_STR * 2;
    const int ju = j0 + wn * 8 + u;
    const int b0 = bbase + mrow + r;

    float bias[4][2];
#pragma unroll
    for (int g = 0; g < 4; g++) {
        bias[g][0] = bhh[g * 512 + ju];
        bias[g][1] = bhh[g * 512 + ju + 1];
    }
    float c[4] = {0.f, 0.f, 0.f, 0.f};

    uint32_t xrn[4][2];
    {
        const int t0 = (L0 && dir) ? (TT - 1) : 0;
        const __half* xp = xg + ((size_t)t0 * BB + b0) * G4H + ju;
#pragma unroll
        for (int g = 0; g < 4; g++)
#pragma unroll
            for (int rp = 0; rp < 2; rp++)
                xrn[g][rp] = *(const uint32_t*)(xp + (size_t)rp * 8 * G4H + g * 512);
    }

    for (int step = 0; step < TT; step++) {
        const int t = (L0 && dir) ? (TT - 1 - step) : step;

        uint32_t xr[4][2];
#pragma unroll
        for (int g = 0; g < 4; g++)
#pragma unroll
            for (int rp = 0; rp < 2; rp++) xr[g][rp] = xrn[g][rp];

        float acc[4][4];
#pragma unroll
        for (int g = 0; g < 4; g++)
#pragma unroll
            for (int k = 0; k < 4; k++) acc[g][k] = 0.f;

        if (step > 0) {
            const int rpar = (step - 1) & 1;
            const __half* hs = hbuf + (size_t)rpar * BB * HH;
            stage64(AB0, hs, bbase, 0, tid);   CP_COMMIT;
            stage64(AB1, hs, bbase, 256, tid); CP_COMMIT;
            CP_WAIT_1;
            __syncthreads();
            mma_chunk_hi(AB0, WHIb, mrow, 0, a_row, a_col, b_n, b_k, acc);
            CP_WAIT_0;
            __syncthreads();
            mma_chunk_hi(AB1, WHIb, mrow, 256, a_row, a_col, b_n, b_k, acc);
        }

        {
            const int wpar = step & 1;
            __half* dh = hbuf + (size_t)wpar * BB * HH;
#pragma unroll
            for (int rp = 0; rp < 2; rp++) {
                const int b = b0 + rp * 8;
                float hv2[2];
#pragma unroll
                for (int cc = 0; cc < 2; cc++) {
                    const int k = rp * 2 + cc;
                    float2 x0 = __half22float2(*(__half2*)&xr[0][rp]);
                    float2 x1 = __half22float2(*(__half2*)&xr[1][rp]);
                    float2 x2 = __half22float2(*(__half2*)&xr[2][rp]);
                    float2 x3 = __half22float2(*(__half2*)&xr[3][rp]);
                    float gi = acc[0][k] + (cc ? x0.y : x0.x) + bias[0][cc];
                    float gf = acc[1][k] + (cc ? x1.y : x1.x) + bias[1][cc];
                    float gg = acc[2][k] + (cc ? x2.y : x2.x) + bias[2][cc];
                    float go = acc[3][k] + (cc ? x3.y : x3.x) + bias[3][cc];
                    float cv = sigmoidf_(gf) * c[k] + sigmoidf_(gi) * tanhf(gg);
                    c[k] = cv;
                    hv2[cc] = sigmoidf_(go) * tanhf(cv);
                }
                uint32_t p = pack_h2(hv2[0], hv2[1]);
                *(uint32_t*)(dh + (size_t)b * HH + ju) = p;
                if (L0) {
                    *(uint32_t*)(houth + ((size_t)t * BB + b) * 1024 + dir * 512 + ju) = p;
                } else if (t == TT - 1) {
                    *(float2*)(houtf + (size_t)b * HH + ju) =
                        make_float2(hv2[0], hv2[1]);
                }
            }
        }

        if (step < TT - 1) {
            {
                const int tn = (L0 && dir) ? (TT - 2 - step) : (step + 1);
                const __half* xp = xg + ((size_t)tn * BB + b0) * G4H + ju;
#pragma unroll
                for (int g = 0; g < 4; g++)
#pragma unroll
                    for (int rp = 0; rp < 2; rp++)
                        xrn[g][rp] = *(const uint32_t*)(xp + (size_t)rp * 8 * G4H + g * 512);
            }
            __threadfence();
            __syncthreads();
            if (tid == 0)
                bar_arrive_wait(barp + step * BAR_STEP, bsub, 64);
            __syncthreads();
        }
    }
}

// ========================= layer-1 reverse at t = T-1 ========================
__global__ void hr_last_kernel(const __half* __restrict__ xg,
                               const float* __restrict__ bhh,
                               float* __restrict__ hr) {
    int idx = blockIdx.x * blockDim.x + threadIdx.x;
    if (idx >= BB * HH) return;
    int b = idx >> 9, j = idx & 511;
    float gi = __half2float(xg[(size_t)b * G4H + j])        + bhh[j];
    float gg = __half2float(xg[(size_t)b * G4H + 1024 + j]) + bhh[1024 + j];
    float go = __half2float(xg[(size_t)b * G4H + 1536 + j]) + bhh[1536 + j];
    float cv = sigmoidf_(gi) * tanhf(gg);
    hr[idx] = sigmoidf_(go) * tanhf(cv);
}

// ========================= final projection ==================================
__global__ void out_kernel(const float* __restrict__ hf, const float* __restrict__ hr,
                           const float* __restrict__ wout, const float* __restrict__ bout,
                           float* __restrict__ out) {
    int b = blockIdx.x;
    int warp = threadIdx.x >> 5;
    int lane = threadIdx.x & 31;
    float s = 0.f;
    for (int k = lane; k < 512; k += 32) s += hf[(size_t)b * HH + k] * wout[warp * 1024 + k];
    for (int k = lane; k < 512; k += 32) s += hr[(size_t)b * HH + k] * wout[warp * 1024 + 512 + k];
#pragma unroll
    for (int off = 16; off; off >>= 1) s += __shfl_xor_sync(0xffffffffu, s, off);
    if (lane == 0) out[b * NCLS + warp] = s + bout[warp];
}

// ========================= host launch =======================================
extern "C" void kernel_launch(void* const* d_in, const int* in_sizes, int n_in,
                              void* d_out, int out_size) {
    const int*   x     = (const int*)  d_in[0];
    const float* emb   = (const float*)d_in[1];
    const float* wih0f = (const float*)d_in[2];
    const float* whh0f = (const float*)d_in[3];
    const float* bih0f = (const float*)d_in[4];
    const float* bhh0f = (const float*)d_in[5];
    const float* wih0r = (const float*)d_in[6];
    const float* whh0r = (const float*)d_in[7];
    const float* bih0r = (const float*)d_in[8];
    const float* bhh0r = (const float*)d_in[9];
    const float* wih1f = (const float*)d_in[10];
    const float* whh1f = (const float*)d_in[11];
    const float* bih1f = (const float*)d_in[12];
    const float* bhh1f = (const float*)d_in[13];
    const float* wih1r = (const float*)d_in[14];
    const float* whh1r = (const float*)d_in[15]; (void)whh1r;
    const float* bih1r = (const float*)d_in[16];
    const float* bhh1r = (const float*)d_in[17];
    const float* wout  = (const float*)d_in[18];
    const float* bout  = (const float*)d_in[19];
    float* out = (float*)d_out;

    __half *p_x0, *p_h0, *p_hf0, *p_hf1, *p_xg0f, *p_xg0r, *p_xg1f, *p_xg1r;
    float *p_h1f, *p_hr1;
    int *p_bar0, *p_bar1;
    cudaGetSymbolAddress((void**)&p_x0,   g_x0);
    cudaGetSymbolAddress((void**)&p_xg0f, g_xg0f);
    cudaGetSymbolAddress((void**)&p_xg0r, g_xg0r);
    cudaGetSymbolAddress((void**)&p_h0,   g_h0);
    cudaGetSymbolAddress((void**)&p_xg1f, g_xg1f);
    cudaGetSymbolAddress((void**)&p_xg1r, g_xg1r);
    cudaGetSymbolAddress((void**)&p_hf0,  g_hf0);
    cudaGetSymbolAddress((void**)&p_hf1,  g_hf1);
    cudaGetSymbolAddress((void**)&p_h1f,  g_h1f);
    cudaGetSymbolAddress((void**)&p_hr1,  g_hr1);
    cudaGetSymbolAddress((void**)&p_bar0, g_bar0);
    cudaGetSymbolAddress((void**)&p_bar1, g_bar1);

    cudaFuncSetAttribute(scan_bs<true>,  cudaFuncAttributeMaxDynamicSharedMemorySize, SCAN_SMEM);
    cudaFuncSetAttribute(scan_bs<false>, cudaFuncAttributeMaxDynamicSharedMemorySize, SCAN_SMEM);

    reset_kernel<<<128, 256>>>();
    embed_kernel<<<(TT * BB * (DEMB / 4) + 255) / 256, 256>>>(x, emb, p_x0);

    dim3 gBig(G4H / 128, (TT * BB) / 128);   // (16, 256)
    gemm_mma<<<gBig, 256>>>(p_x0, wih0f, bih0f, p_xg0f, TT * BB, G4H, DEMB);
    gemm_mma<<<gBig, 256>>>(p_x0, wih0r, bih0r, p_xg0r, TT * BB, G4H, DEMB);

    scan_bs<true><<<128, 256, SCAN_SMEM>>>(p_xg0f, p_xg0r, whh0f, whh0r,
                                           bhh0f, bhh0r, p_hf0, p_h0,
                                           nullptr, p_bar0);

    gemm_mma<<<gBig, 256>>>(p_h0, wih1f, bih1f, p_xg1f, TT * BB, G4H, 2 * HH);
    gemm_mma<<<dim3(G4H / 128, 1), 256>>>(
        p_h0 + (size_t)(TT - 1) * BB * 1024, wih1r, bih1r, p_xg1r, BB, G4H, 2 * HH);

    scan_bs<false><<<64, 256, SCAN_SMEM>>>(p_xg1f, p_xg1f, whh1f, whh1f,
                                           bhh1f, bhh1f, p_hf1, nullptr,
                                           p_h1f, p_bar1);

    hr_last_kernel<<<(BB * HH) / 256, 256>>>(p_xg1r, bhh1r, p_hr1);

    out_kernel<<<BB, 160>>>(p_h1f, p_hr1, wout, bout, out);
}

// round 17
// speedup vs baseline: 1.2316x; 1.0162x over previous
#include <cuda_runtime.h>
#include <cuda_fp16.h>
#include <math.h>
#include <cstdint>

#define TT 256
#define BB 128
#define HH 512
#define DEMB 256
#define PAD_IDX 29999
#define NCLS 5
#define G4H 2048  // 4*HH

#define BAR_SUB 8
#define BAR_SPC 32
#define BAR_STEP (BAR_SUB * BAR_SPC)
#define BAR_GRP  (TT * BAR_STEP)

// pre-split W plane offsets (elements)
#define O0F 0
#define O0R (2048 * 256)
#define O1F (2 * 2048 * 256)
#define O1R (O1F + 2048 * 1024)
#define OW_TOTAL (O1R + 2048 * 1024)

__device__ __forceinline__ uint32_t smem_to_u32(const void* p) {
    uint32_t a;
    asm("{ .reg .u64 t; cvta.to.shared.u64 t, %1; cvt.u32.u64 %0, t; }" : "=r"(a) : "l"(p));
    return a;
}
#define CP_ASYNC16(dst, src) \
    asm volatile("cp.async.cg.shared.global [%0], [%1], 16;" :: "r"(dst), "l"(src))
#define CP_COMMIT  asm volatile("cp.async.commit_group;" ::: "memory")
#define CP_WAIT_1  asm volatile("cp.async.wait_group 1;" ::: "memory")
#define CP_WAIT_0  asm volatile("cp.async.wait_group 0;" ::: "memory")

// ========================= scratch (static, no allocs) =======================
__device__ __half g_x0 [(size_t)TT * BB * DEMB];
__device__ __half g_xg0f[(size_t)TT * BB * G4H];
__device__ __half g_xg0r[(size_t)TT * BB * G4H];
__device__ __half g_h0 [(size_t)TT * BB * 2 * HH];
__device__ __half g_xg1f[(size_t)TT * BB * G4H];
__device__ __half g_xg1r[(size_t)BB * G4H];
__device__ __half g_hf0[2 * 2 * BB * HH];
__device__ __half g_hf1[2 * BB * HH];
__device__ float g_h1f [BB * HH];
__device__ float g_hr1 [BB * HH];
__device__ __half g_whi[OW_TOTAL];
__device__ __half g_wlo[OW_TOTAL];
__device__ int g_bar0[2 * BAR_GRP];
__device__ int g_bar1[BAR_GRP];

__global__ void reset_kernel() {
    int n0 = 2 * BAR_GRP;
    for (int i = blockIdx.x * blockDim.x + threadIdx.x; i < n0;
         i += gridDim.x * blockDim.x) {
        g_bar0[i] = 0;
        if (i < BAR_GRP) g_bar1[i] = 0;
    }
}

__device__ __forceinline__ uint32_t pack_h2(float a, float b) {
    __half2 h = __floats2half2_rn(a, b);
    return *(uint32_t*)&h;
}

__device__ __forceinline__ void bar_arrive_wait(int* base, int sub, int target) {
    atomicAdd(base + sub * BAR_SPC, 1);
    for (;;) {
        int sum = 0;
#pragma unroll
        for (int s = 0; s < BAR_SUB; s++) {
            int v;
            asm volatile("ld.global.cg.b32 %0, [%1];" : "=r"(v)
                         : "l"(base + s * BAR_SPC));
            sum += v;
        }
        if (sum >= target) break;
        __nanosleep(32);
    }
}

// ========================= W pre-split (fp32 -> fp16 hi/lo) ==================
__global__ void wsplit_kernel(const float* __restrict__ W,
                              __half* __restrict__ whi,
                              __half* __restrict__ wlo, int n4) {
    int i = blockIdx.x * blockDim.x + threadIdx.x;
    if (i >= n4) return;
    float4 v = ((const float4*)W)[i];
    __half h0 = __float2half_rn(v.x), h1 = __float2half_rn(v.y);
    __half h2 = __float2half_rn(v.z), h3 = __float2half_rn(v.w);
    uint2 hi, lo;
    hi.x = pack_h2(__half2float(h0), __half2float(h1));
    hi.y = pack_h2(__half2float(h2), __half2float(h3));
    lo.x = pack_h2(v.x - __half2float(h0), v.y - __half2float(h1));
    lo.y = pack_h2(v.z - __half2float(h2), v.w - __half2float(h3));
    ((uint2*)whi)[i] = hi;
    ((uint2*)wlo)[i] = lo;
}

// ========================= embedding gather (fp16 out) =======================
__global__ void embed_kernel(const int* __restrict__ x,
                             const float* __restrict__ emb,
                             __half* __restrict__ out) {
    int gid = blockIdx.x * blockDim.x + threadIdx.x;
    if (gid >= TT * BB * (DEMB / 4)) return;
    int i4  = gid & 63;
    int row = gid >> 6;
    int t = row / BB;
    int b = row - t * BB;
    int xi = x[b * TT + t];
    float4 v;
    if (xi == PAD_IDX) { v.x = v.y = v.z = v.w = 0.f; }
    else               { v = ((const float4*)emb)[(size_t)xi * 64 + i4]; }
    uint2 p;
    p.x = pack_h2(v.x, v.y);
    p.y = pack_h2(v.z, v.w);
    ((uint2*)out)[gid] = p;
}

// ========================= mma primitives ====================================
__device__ __forceinline__ void ldsm4(uint32_t* r, uint32_t addr) {
    asm volatile("ldmatrix.sync.aligned.m8n8.x4.shared.b16 {%0,%1,%2,%3}, [%4];"
        : "=r"(r[0]), "=r"(r[1]), "=r"(r[2]), "=r"(r[3]) : "r"(addr));
}
__device__ __forceinline__ void mma_f16(float* d, const uint32_t* a,
                                        uint32_t b0, uint32_t b1) {
    asm volatile("mma.sync.aligned.m16n8k16.row.col.f32.f16.f16.f32 "
        "{%0,%1,%2,%3}, {%4,%5,%6,%7}, {%8,%9}, {%0,%1,%2,%3};"
        : "+f"(d[0]), "+f"(d[1]), "+f"(d[2]), "+f"(d[3])
        : "r"(a[0]), "r"(a[1]), "r"(a[2]), "r"(a[3]), "r"(b0), "r"(b1));
}
__device__ __forceinline__ void wh_store(uint32_t hiA, float4 v) {
    uint32_t hp0 = pack_h2(v.x, v.y);
    uint32_t hp1 = pack_h2(v.z, v.w);
    asm volatile("st.shared.v2.b32 [%0], {%1, %2};" :: "r"(hiA), "r"(hp0), "r"(hp1) : "memory");
}

// ========================= GEMM: C(fp16) = A*W^T + bias (pre-split W) ========
// A fp16 [M,K], Whi/Wlo fp16 [N,K]; all staged via cp.async, double-buffered.
#define KC  32
#define LDH 40
#define GB_BYTES (128 * LDH * 2)   // 10240 per buffer

__global__ __launch_bounds__(256, 2) void gemm_mma(const __half* __restrict__ A,
                                                   const __half* __restrict__ Whi,
                                                   const __half* __restrict__ Wlo,
                                                   const float* __restrict__ bias,
                                                   __half* __restrict__ C,
                                                   int M, int N, int K) {
    extern __shared__ __align__(16) __half gsm[];
    const uint32_t sb  = smem_to_u32(gsm);
    const uint32_t AH0 = sb,                AH1 = sb + GB_BYTES;
    const uint32_t WH0 = sb + 2 * GB_BYTES, WH1 = sb + 3 * GB_BYTES;
    const uint32_t WL0 = sb + 4 * GB_BYTES, WL1 = sb + 5 * GB_BYTES;

    const int tid  = threadIdx.x;
    const int lane = tid & 31;
    const int wid  = tid >> 5;
    const int wm   = wid & 3;
    const int wn   = wid >> 2;
    const int bm   = blockIdx.y * 128;
    const int bn   = blockIdx.x * 128;

    float acc[2][8][4];
#pragma unroll
    for (int i = 0; i < 2; i++)
#pragma unroll
        for (int j = 0; j < 8; j++)
#pragma unroll
            for (int k = 0; k < 4; k++) acc[i][j][k] = 0.f;

    const uint32_t a_row = lane & 15;
    const uint32_t a_col = (lane >> 4) << 3;
    const uint32_t b_n   = (lane & 7) + ((lane >> 4) << 3);
    const uint32_t b_k   = ((lane >> 3) & 1) << 3;

    const int s_row = tid >> 2, s_c8 = tid & 3;   // 128 rows x 4 segs, 2 iters

    // prologue: stage chunk 0 (A + Whi + Wlo)
#pragma unroll
    for (int i = 0; i < 2; i++) {
        int e = tid + i * 256;
        int row = e >> 2, seg = e & 3;
        uint32_t doff = (row * LDH + seg * 8) * 2;
        CP_ASYNC16(AH0 + doff, A   + (size_t)(bm + row) * K + seg * 8);
        CP_ASYNC16(WH0 + doff, Whi + (size_t)(bn + row) * K + seg * 8);
        CP_ASYNC16(WL0 + doff, Wlo + (size_t)(bn + row) * K + seg * 8);
    }
    CP_COMMIT;
    (void)s_row; (void)s_c8;

    const int nch = K / KC;
    for (int ch = 0; ch < nch; ch++) {
        const int kb = ch * KC;
        if (ch + 1 < nch) {
            const int alt = (ch + 1) & 1;
            const uint32_t AHd = alt ? AH1 : AH0;
            const uint32_t WHd = alt ? WH1 : WH0;
            const uint32_t WLd = alt ? WL1 : WL0;
#pragma unroll
            for (int i = 0; i < 2; i++) {
                int e = tid + i * 256;
                int row = e >> 2, seg = e & 3;
                uint32_t doff = (row * LDH + seg * 8) * 2;
                CP_ASYNC16(AHd + doff, A   + (size_t)(bm + row) * K + kb + KC + seg * 8);
                CP_ASYNC16(WHd + doff, Whi + (size_t)(bn + row) * K + kb + KC + seg * 8);
                CP_ASYNC16(WLd + doff, Wlo + (size_t)(bn + row) * K + kb + KC + seg * 8);
            }
            CP_COMMIT;
            CP_WAIT_1;
        } else {
            CP_WAIT_0;
        }
        __syncthreads();

        const int cur = ch & 1;
        const uint32_t AH  = cur ? AH1 : AH0;
        const uint32_t WHc = cur ? WH1 : WH0;
        const uint32_t WLc = cur ? WL1 : WL0;
#pragma unroll
        for (int ks = 0; ks < KC; ks += 16) {
            uint32_t ah[2][4];
#pragma unroll
            for (int ma = 0; ma < 2; ma++)
                ldsm4(ah[ma], AH + ((wm * 32 + ma * 16 + a_row) * LDH + ks + a_col) * 2);
#pragma unroll
            for (int bg = 0; bg < 4; bg++) {
                uint32_t boff = ((wn * 64 + bg * 16 + b_n) * LDH + ks + b_k) * 2;
                uint32_t bh[4], bl[4];
                ldsm4(bh, WHc + boff);
                ldsm4(bl, WLc + boff);
#pragma unroll
                for (int ma = 0; ma < 2; ma++) {
#pragma unroll
                    for (int na = 0; na < 2; na++) {
                        float* d = acc[ma][bg * 2 + na];
                        mma_f16(d, ah[ma], bh[na * 2], bh[na * 2 + 1]);
                        mma_f16(d, ah[ma], bl[na * 2], bl[na * 2 + 1]);
                    }
                }
            }
        }
        __syncthreads();
    }

#pragma unroll
    for (int ma = 0; ma < 2; ma++) {
        int row0 = bm + wm * 32 + ma * 16 + (lane >> 2);
#pragma unroll
        for (int na = 0; na < 8; na++) {
            int col = bn + wn * 64 + na * 8 + (lane & 3) * 2;
            float b0 = bias[col], b1 = bias[col + 1];
            *(uint32_t*)(C + (size_t)row0 * N + col) =
                pack_h2(acc[ma][na][0] + b0, acc[ma][na][1] + b1);
            *(uint32_t*)(C + (size_t)(row0 + 8) * N + col) =
                pack_h2(acc[ma][na][2] + b0, acc[ma][na][3] + b1);
        }
    }
}
#define GEMM_SMEM (6 * GB_BYTES)   // 61440

__device__ __forceinline__ float sigmoidf_(float v) { return 1.f / (1.f + expf(-v)); }

// ========================= scan (batch-split, W hi-only, unified) ============
#define W_STR 520
#define A_STR 264
#define S0_W_BYTES (64 * W_STR * 2)
#define S0_ABUF (64 * A_STR * 2)
#define SCAN_SMEM (S0_W_BYTES + 2 * S0_ABUF)

__device__ __forceinline__ void stage64(uint32_t dst, const __half* hs,
                                        int bbase, int kb, int tid) {
#pragma unroll
    for (int i = 0; i < 8; i++) {
        int e = tid + i * 256;
        int row = e >> 5, seg = e & 31;
        const __half* src = hs + (size_t)(bbase + row) * HH + kb + seg * 8;
        CP_ASYNC16(dst + (row * A_STR + seg * 8) * 2, src);
    }
}

__device__ __forceinline__ void mma_chunk_hi(uint32_t AB, uint32_t WHIb,
                                             int mrow, int kg0,
                                             uint32_t a_row, uint32_t a_col,
                                             uint32_t b_n, uint32_t b_k,
                                             float acc[4][4]) {
#pragma unroll
    for (int kk = 0; kk < 16; kk++) {
        uint32_t a[4];
        ldsm4(a, AB + ((mrow + a_row) * A_STR + kk * 16 + a_col) * 2);
        int kg = kg0 + kk * 16;
        uint32_t bh0[4], bh1[4];
        ldsm4(bh0, WHIb + (b_n * W_STR + kg + b_k) * 2);
        ldsm4(bh1, WHIb + ((16 + b_n) * W_STR + kg + b_k) * 2);
        mma_f16(acc[0], a, bh0[0], bh0[1]);
        mma_f16(acc[1], a, bh0[2], bh0[3]);
        mma_f16(acc[2], a, bh1[0], bh1[1]);
        mma_f16(acc[3], a, bh1[2], bh1[3]);
    }
}

template<bool L0>
__global__ __launch_bounds__(256, 1) void scan_bs(
    const __half* __restrict__ xgf, const __half* __restrict__ xgr,
    const float* __restrict__ whhf, const float* __restrict__ whhr,
    const float* __restrict__ bhhf, const float* __restrict__ bhhr,
    __half* __restrict__ hrec, __half* __restrict__ houth,
    float* __restrict__ houtf, int* __restrict__ bar) {
    extern __shared__ __align__(16) char smem[];
    const uint32_t sb  = smem_to_u32(smem);
    const uint32_t WHI = sb;
    const uint32_t AB0 = sb + S0_W_BYTES, AB1 = AB0 + S0_ABUF;

    const int tid = threadIdx.x, lane = tid & 31, wid = tid >> 5;
    const int dir   = L0 ? (int)(blockIdx.x >> 6) : 0;
    const int rest  = L0 ? (int)(blockIdx.x & 63) : (int)blockIdx.x;
    const int slice = rest >> 1;
    const int bg    = rest & 1;
    const int j0    = slice * 16;
    const int bbase = bg * 64;
    const int bsub  = rest & 7;

    const float* whh = (L0 && dir) ? whhr : whhf;
    const float* bhh = (L0 && dir) ? bhhr : bhhf;
    const __half* xg = (L0 && dir) ? xgr  : xgf;
    int* barp = bar + (L0 ? dir * BAR_GRP : 0);
    __half* hbuf = hrec + (L0 ? (size_t)dir * 2 * BB * HH : 0);

#pragma unroll
    for (int i = 0; i < 32; i++) {
        int idx = tid + i * 256;
        int n = idx >> 7, c4 = idx & 127;
        int wn_ = n >> 5, m5 = n & 31;
        int grow = (m5 >> 3) * 512 + j0 + wn_ * 8 + (m5 & 7);
        float4 v = *(const float4*)(whh + (size_t)grow * 512 + c4 * 4);
        wh_store(WHI + (n * W_STR + c4 * 4) * 2, v);
    }
    __syncthreads();

    const uint32_t a_row = lane & 15;
    const uint32_t a_col = (lane >> 4) << 3;
    const uint32_t b_n   = (lane & 7) + ((lane >> 4) << 3);
    const uint32_t b_k   = ((lane >> 3) & 1) << 3;
    const int r = lane >> 2;
    const int u = (lane & 3) * 2;
    const int wm = wid & 3;
    const int wn = wid >> 2;
    const int mrow = wm * 16;
    const uint32_t WHIb = WHI + wn * 32 * W_STR * 2;
    const int ju = j0 + wn * 8 + u;
    const int b0 = bbase + mrow + r;

    float bias[4][2];
#pragma unroll
    for (int g = 0; g < 4; g++) {
        bias[g][0] = bhh[g * 512 + ju];
        bias[g][1] = bhh[g * 512 + ju + 1];
    }
    float c[4] = {0.f, 0.f, 0.f, 0.f};

    uint32_t xrn[4][2];
    {
        const int t0 = (L0 && dir) ? (TT - 1) : 0;
        const __half* xp = xg + ((size_t)t0 * BB + b0) * G4H + ju;
#pragma unroll
        for (int g = 0; g < 4; g++)
#pragma unroll
            for (int rp = 0; rp < 2; rp++)
                xrn[g][rp] = *(const uint32_t*)(xp + (size_t)rp * 8 * G4H + g * 512);
    }

    for (int step = 0; step < TT; step++) {
        const int t = (L0 && dir) ? (TT - 1 - step) : step;

        uint32_t xr[4][2];
#pragma unroll
        for (int g = 0; g < 4; g++)
#pragma unroll
            for (int rp = 0; rp < 2; rp++) xr[g][rp] = xrn[g][rp];

        float acc[4][4];
#pragma unroll
        for (int g = 0; g < 4; g++)
#pragma unroll
            for (int k = 0; k < 4; k++) acc[g][k] = 0.f;

        if (step > 0) {
            const int rpar = (step - 1) & 1;
            const __half* hs = hbuf + (size_t)rpar * BB * HH;
            stage64(AB0, hs, bbase, 0, tid);   CP_COMMIT;
            stage64(AB1, hs, bbase, 256, tid); CP_COMMIT;
            CP_WAIT_1;
            __syncthreads();
            mma_chunk_hi(AB0, WHIb, mrow, 0, a_row, a_col, b_n, b_k, acc);
            CP_WAIT_0;
            __syncthreads();
            mma_chunk_hi(AB1, WHIb, mrow, 256, a_row, a_col, b_n, b_k, acc);
        }

        {
            const int wpar = step & 1;
            __half* dh = hbuf + (size_t)wpar * BB * HH;
#pragma unroll
            for (int rp = 0; rp < 2; rp++) {
                const int b = b0 + rp * 8;
                float hv2[2];
#pragma unroll
                for (int cc = 0; cc < 2; cc++) {
                    const int k = rp * 2 + cc;
                    float2 x0 = __half22float2(*(__half2*)&xr[0][rp]);
                    float2 x1 = __half22float2(*(__half2*)&xr[1][rp]);
                    float2 x2 = __half22float2(*(__half2*)&xr[2][rp]);
                    float2 x3 = __half22float2(*(__half2*)&xr[3][rp]);
                    float gi = acc[0][k] + (cc ? x0.y : x0.x) + bias[0][cc];
                    float gf = acc[1][k] + (cc ? x1.y : x1.x) + bias[1][cc];
                    float gg = acc[2][k] + (cc ? x2.y : x2.x) + bias[2][cc];
                    float go = acc[3][k] + (cc ? x3.y : x3.x) + bias[3][cc];
                    float cv = sigmoidf_(gf) * c[k] + sigmoidf_(gi) * tanhf(gg);
                    c[k] = cv;
                    hv2[cc] = sigmoidf_(go) * tanhf(cv);
                }
                uint32_t p = pack_h2(hv2[0], hv2[1]);
                *(uint32_t*)(dh + (size_t)b * HH + ju) = p;
                if (L0) {
                    *(uint32_t*)(houth + ((size_t)t * BB + b) * 1024 + dir * 512 + ju) = p;
                } else if (t == TT - 1) {
                    *(float2*)(houtf + (size_t)b * HH + ju) =
                        make_float2(hv2[0], hv2[1]);
                }
            }
        }

        if (step < TT - 1) {
            {
                const int tn = (L0 && dir) ? (TT - 2 - step) : (step + 1);
                const __half* xp = xg + ((size_t)tn * BB + b0) * G4H + ju;
#pragma unroll
                for (int g = 0; g < 4; g++)
#pragma unroll
                    for (int rp = 0; rp < 2; rp++)
                        xrn[g][rp] = *(const uint32_t*)(xp + (size_t)rp * 8 * G4H + g * 512);
            }
            __threadfence();
            __syncthreads();
            if (tid == 0)
                bar_arrive_wait(barp + step * BAR_STEP, bsub, 64);
            __syncthreads();
        }
    }
}

// ========================= layer-1 reverse at t = T-1 ========================
__global__ void hr_last_kernel(const __half* __restrict__ xg,
                               const float* __restrict__ bhh,
                               float* __restrict__ hr) {
    int idx = blockIdx.x * blockDim.x + threadIdx.x;
    if (idx >= BB * HH) return;
    int b = idx >> 9, j = idx & 511;
    float gi = __half2float(xg[(size_t)b * G4H + j])        + bhh[j];
    float gg = __half2float(xg[(size_t)b * G4H + 1024 + j]) + bhh[1024 + j];
    float go = __half2float(xg[(size_t)b * G4H + 1536 + j]) + bhh[1536 + j];
    float cv = sigmoidf_(gi) * tanhf(gg);
    hr[idx] = sigmoidf_(go) * tanhf(cv);
}

// ========================= final projection ==================================
__global__ void out_kernel(const float* __restrict__ hf, const float* __restrict__ hr,
                           const float* __restrict__ wout, const float* __restrict__ bout,
                           float* __restrict__ out) {
    int b = blockIdx.x;
    int warp = threadIdx.x >> 5;
    int lane = threadIdx.x & 31;
    float s = 0.f;
    for (int k = lane; k < 512; k += 32) s += hf[(size_t)b * HH + k] * wout[warp * 1024 + k];
    for (int k = lane; k < 512; k += 32) s += hr[(size_t)b * HH + k] * wout[warp * 1024 + 512 + k];
#pragma unroll
    for (int off = 16; off; off >>= 1) s += __shfl_xor_sync(0xffffffffu, s, off);
    if (lane == 0) out[b * NCLS + warp] = s + bout[warp];
}

// ========================= host launch =======================================
extern "C" void kernel_launch(void* const* d_in, const int* in_sizes, int n_in,
                              void* d_out, int out_size) {
    const int*   x     = (const int*)  d_in[0];
    const float* emb   = (const float*)d_in[1];
    const float* wih0f = (const float*)d_in[2];
    const float* whh0f = (const float*)d_in[3];
    const float* bih0f = (const float*)d_in[4];
    const float* bhh0f = (const float*)d_in[5];
    const float* wih0r = (const float*)d_in[6];
    const float* whh0r = (const float*)d_in[7];
    const float* bih0r = (const float*)d_in[8];
    const float* bhh0r = (const float*)d_in[9];
    const float* wih1f = (const float*)d_in[10];
    const float* whh1f = (const float*)d_in[11];
    const float* bih1f = (const float*)d_in[12];
    const float* bhh1f = (const float*)d_in[13];
    const float* wih1r = (const float*)d_in[14];
    const float* whh1r = (const float*)d_in[15]; (void)whh1r;
    const float* bih1r = (const float*)d_in[16];
    const float* bhh1r = (const float*)d_in[17];
    const float* wout  = (const float*)d_in[18];
    const float* bout  = (const float*)d_in[19];
    float* out = (float*)d_out;

    __half *p_x0, *p_h0, *p_hf0, *p_hf1, *p_xg0f, *p_xg0r, *p_xg1f, *p_xg1r;
    __half *p_whi, *p_wlo;
    float *p_h1f, *p_hr1;
    int *p_bar0, *p_bar1;
    cudaGetSymbolAddress((void**)&p_x0,   g_x0);
    cudaGetSymbolAddress((void**)&p_xg0f, g_xg0f);
    cudaGetSymbolAddress((void**)&p_xg0r, g_xg0r);
    cudaGetSymbolAddress((void**)&p_h0,   g_h0);
    cudaGetSymbolAddress((void**)&p_xg1f, g_xg1f);
    cudaGetSymbolAddress((void**)&p_xg1r, g_xg1r);
    cudaGetSymbolAddress((void**)&p_hf0,  g_hf0);
    cudaGetSymbolAddress((void**)&p_hf1,  g_hf1);
    cudaGetSymbolAddress((void**)&p_h1f,  g_h1f);
    cudaGetSymbolAddress((void**)&p_hr1,  g_hr1);
    cudaGetSymbolAddress((void**)&p_whi,  g_whi);
    cudaGetSymbolAddress((void**)&p_wlo,  g_wlo);
    cudaGetSymbolAddress((void**)&p_bar0, g_bar0);
    cudaGetSymbolAddress((void**)&p_bar1, g_bar1);

    cudaFuncSetAttribute(gemm_mma,       cudaFuncAttributeMaxDynamicSharedMemorySize, GEMM_SMEM);
    cudaFuncSetAttribute(scan_bs<true>,  cudaFuncAttributeMaxDynamicSharedMemorySize, SCAN_SMEM);
    cudaFuncSetAttribute(scan_bs<false>, cudaFuncAttributeMaxDynamicSharedMemorySize, SCAN_SMEM);

    reset_kernel<<<128, 256>>>();
    embed_kernel<<<(TT * BB * (DEMB / 4) + 255) / 256, 256>>>(x, emb, p_x0);

    // W pre-split (once per launch; bit-identical to old in-GEMM splitting)
    wsplit_kernel<<<(2048 * 256 / 4 + 255) / 256, 256>>>(wih0f, p_whi + O0F, p_wlo + O0F, 2048 * 256 / 4);
    wsplit_kernel<<<(2048 * 256 / 4 + 255) / 256, 256>>>(wih0r, p_whi + O0R, p_wlo + O0R, 2048 * 256 / 4);
    wsplit_kernel<<<(2048 * 1024 / 4 + 255) / 256, 256>>>(wih1f, p_whi + O1F, p_wlo + O1F, 2048 * 1024 / 4);
    wsplit_kernel<<<(2048 * 1024 / 4 + 255) / 256, 256>>>(wih1r, p_whi + O1R, p_wlo + O1R, 2048 * 1024 / 4);

    dim3 gBig(G4H / 128, (TT * BB) / 128);   // (16, 256)
    gemm_mma<<<gBig, 256, GEMM_SMEM>>>(p_x0, p_whi + O0F, p_wlo + O0F, bih0f,
                                       p_xg0f, TT * BB, G4H, DEMB);
    gemm_mma<<<gBig, 256, GEMM_SMEM>>>(p_x0, p_whi + O0R, p_wlo + O0R, bih0r,
                                       p_xg0r, TT * BB, G4H, DEMB);

    scan_bs<true><<<128, 256, SCAN_SMEM>>>(p_xg0f, p_xg0r, whh0f, whh0r,
                                           bhh0f, bhh0r, p_hf0, p_h0,
                                           nullptr, p_bar0);

    gemm_mma<<<gBig, 256, GEMM_SMEM>>>(p_h0, p_whi + O1F, p_wlo + O1F, bih1f,
                                       p_xg1f, TT * BB, G4H, 2 * HH);
    gemm_mma<<<dim3(G4H / 128, 1), 256, GEMM_SMEM>>>(
        p_h0 + (size_t)(TT - 1) * BB * 1024, p_whi + O1R, p_wlo + O1R, bih1r,
        p_xg1r, BB, G4H, 2 * HH);

    scan_bs<false><<<64, 256, SCAN_SMEM>>>(p_xg1f, p_xg1f, whh1f, whh1f,
                                           bhh1f, bhh1f, p_hf1, nullptr,
                                           p_h1f, p_bar1);

    hr_last_kernel<<<(BB * HH) / 256, 256>>>(p_xg1r, bhh1r, p_hr1);

    out_kernel<<<BB, 160>>>(p_h1f, p_hr1, wout, bout, out);
}